// round 8
// baseline (speedup 1.0000x reference)
#include <cuda_runtime.h>
#include <cuda_fp16.h>
#include <cuda_bf16.h>
#include <cstdint>

// Problem constants
#define Bsz 2
#define Lseq 1024
#define DIN 512
#define DM 1024
#define NLAYER 4
#define Eexp 2048
#define Nst 16
#define Rrank 64
#define Kconv 4
#define Mrows (Bsz*Lseq)   // 2048
#define XPSPLIT 8          // split-K factor for xproj

// ---------------- scratch (device globals; no allocation allowed) ----------
__device__ float g_h   [Mrows*DM];
__device__ float g_xz  [Mrows*2*Eexp];
__device__ float g_xm  [Mrows*Eexp];
__device__ float g_xdbl[Mrows*96];
__device__ float g_xp  [XPSPLIT*Mrows*96];   // xproj split-K partials
__device__ float g_dt  [Mrows*Eexp];
__device__ __half g_hnh[Mrows*DM];
__device__ __half g_ygh[Mrows*Eexp];
__device__ __half g_xh [Mrows*DIN];
// converted weights: ip | inproj | outproj | op
#define WOFF_IP      0
#define WOFF_INPROJ  (WOFF_IP + DM*DIN)
#define WOFF_OUTPROJ (WOFF_INPROJ + NLAYER*2*Eexp*DM)
#define WOFF_OP      (WOFF_OUTPROJ + NLAYER*DM*Eexp)
#define WTOTAL       (WOFF_OP + DIN*DM)
__device__ __half g_wh[WTOTAL];

// ---------------- small PTX helpers ----------------------------------------
__device__ __forceinline__ uint32_t smem_u32(const void* p) {
    return (uint32_t)__cvta_generic_to_shared(p);
}
__device__ __forceinline__ void cp_async16(uint32_t dst, const void* src) {
    asm volatile("cp.async.cg.shared.global [%0], [%1], 16;\n"
                 :: "r"(dst), "l"(src));
}
__device__ __forceinline__ void cp_async16g(uint32_t dst, const void* src, int src_bytes) {
    asm volatile("cp.async.cg.shared.global [%0], [%1], 16, %2;\n"
                 :: "r"(dst), "l"(src), "r"(src_bytes));
}
__device__ __forceinline__ void cp_commit() {
    asm volatile("cp.async.commit_group;\n");
}
template<int NPend>
__device__ __forceinline__ void cp_wait() {
    asm volatile("cp.async.wait_group %0;\n" :: "n"(NPend));
}
__device__ __forceinline__ void ldsm_x4(uint32_t& r0, uint32_t& r1,
                                        uint32_t& r2, uint32_t& r3, uint32_t addr) {
    asm volatile("ldmatrix.sync.aligned.m8n8.x4.shared.b16 {%0,%1,%2,%3}, [%4];"
                 : "=r"(r0), "=r"(r1), "=r"(r2), "=r"(r3) : "r"(addr));
}
__device__ __forceinline__ void mma_f16(float* d, const uint32_t* a, const uint32_t* b) {
    asm volatile(
        "mma.sync.aligned.m16n8k16.row.col.f32.f16.f16.f32 "
        "{%0,%1,%2,%3}, {%4,%5,%6,%7}, {%8,%9}, {%0,%1,%2,%3};\n"
        : "+f"(d[0]), "+f"(d[1]), "+f"(d[2]), "+f"(d[3])
        : "r"(a[0]), "r"(a[1]), "r"(a[2]), "r"(a[3]), "r"(b[0]), "r"(b[1]));
}
__device__ __forceinline__ void mma_tf32(float* d, const uint32_t* a, const uint32_t* b) {
    asm volatile(
        "mma.sync.aligned.m16n8k8.row.col.f32.tf32.tf32.f32 "
        "{%0,%1,%2,%3}, {%4,%5,%6,%7}, {%8,%9}, {%0,%1,%2,%3};\n"
        : "+f"(d[0]), "+f"(d[1]), "+f"(d[2]), "+f"(d[3])
        : "r"(a[0]), "r"(a[1]), "r"(a[2]), "r"(a[3]), "r"(b[0]), "r"(b[1]));
}

// =================== fp16 tensor-core NT GEMM ==============================
// C[m,n] = sum_k A[m,k]*W[n,k]; 4-stage cp.async pipeline, prefetch-first.
// M,N multiples of 128; K multiple of 32.  EPI: 0 store, 1 +bias, 3 C += acc
#define HRS 40                              // smem row stride in halfs (80 B)
#define HSTAGE_H (128*HRS)
#define HSTAGE_BYTES (HSTAGE_H*2)           // 10240
#define HSTAGES 4
#define HSMEM_TOTAL (2*HSTAGES*HSTAGE_BYTES)  // 81920

template<int EPI>
__global__ void __launch_bounds__(256, 2)
hgemm_nt(const __half* __restrict__ A, int lda,
         const __half* __restrict__ W, int ldw,
         float* __restrict__ C, int ldc,
         int K, const float* __restrict__ bias)
{
    extern __shared__ char smem[];
    __half* As = (__half*)smem;
    __half* Ws = (__half*)(smem + HSTAGES * HSTAGE_BYTES);

    const int tid  = threadIdx.x;
    const int warp = tid >> 5, lane = tid & 31;
    const int bm   = blockIdx.y * 128;
    const int bn   = blockIdx.x * 128;
    const int wm   = warp & 3;
    const int wn   = warp >> 2;
    const int gid  = lane >> 2, tig = lane & 3;

    float acc[2][8][4];
    #pragma unroll
    for (int i = 0; i < 2; i++)
        #pragma unroll
        for (int j = 0; j < 8; j++)
            #pragma unroll
            for (int q = 0; q < 4; q++) acc[i][j][q] = 0.f;

    auto ldA = [&](int s, int kt) {
        #pragma unroll
        for (int t = 0; t < 2; t++) {
            int idx = tid + t * 256;
            int r = idx >> 2, g = idx & 3;
            cp_async16(smem_u32(As + s * HSTAGE_H + r * HRS + g * 8),
                       A + (size_t)(bm + r) * lda + kt * 32 + g * 8);
        }
    };
    auto ldW = [&](int s, int kt) {
        #pragma unroll
        for (int t = 0; t < 2; t++) {
            int idx = tid + t * 256;
            int r = idx >> 2, g = idx & 3;
            cp_async16(smem_u32(Ws + s * HSTAGE_H + r * HRS + g * 8),
                       W + (size_t)(bn + r) * ldw + kt * 32 + g * 8);
        }
    };

    const int nk = K / 32;
    ldA(0, 0); ldW(0, 0); cp_commit();
    ldA(1, 1); ldW(1, 1); cp_commit();
    ldA(2, 2); ldW(2, 2); cp_commit();

    const int arow = wm * 32 + (lane & 15);
    const int acol = (lane >> 4) << 3;
    const int brow = wn * 64 + (lane & 7) + ((lane & 16) >> 1);
    const int bcol = lane & 8;

    for (int it = 0; it < nk; it++) {
        const int s = it & 3;
        cp_wait<2>();              // group `it` complete (it+1, it+2 may pend)
        __syncthreads();           // all warps done reading stage (it+3)&3

        // prefetch FIRST: ~3 compute-phases of latency cover
        if (it + 3 < nk) {
            const int s3 = (it + 3) & 3;
            ldA(s3, it + 3); ldW(s3, it + 3);
        }
        cp_commit();               // one group per iter (may be empty)

        const __half* Asb = As + s * HSTAGE_H;
        const __half* Wsb = Ws + s * HSTAGE_H;

        #pragma unroll
        for (int kk = 0; kk < 32; kk += 16) {
            uint32_t af[2][4];
            #pragma unroll
            for (int mt = 0; mt < 2; mt++)
                ldsm_x4(af[mt][0], af[mt][1], af[mt][2], af[mt][3],
                        smem_u32(Asb + (arow + mt * 16) * HRS + kk + acol));
            uint32_t bf[8][2];
            #pragma unroll
            for (int ntp = 0; ntp < 4; ntp++)
                ldsm_x4(bf[ntp * 2][0], bf[ntp * 2][1],
                        bf[ntp * 2 + 1][0], bf[ntp * 2 + 1][1],
                        smem_u32(Wsb + (brow + ntp * 16) * HRS + kk + bcol));
            #pragma unroll
            for (int mt = 0; mt < 2; mt++)
                #pragma unroll
                for (int nt = 0; nt < 8; nt++)
                    mma_f16(acc[mt][nt], af[mt], bf[nt]);
        }
    }

    #pragma unroll
    for (int mt = 0; mt < 2; mt++) {
        int r0 = bm + wm * 32 + mt * 16 + gid;
        #pragma unroll
        for (int nt = 0; nt < 8; nt++) {
            int n0 = bn + wn * 64 + nt * 8 + tig * 2;
            #pragma unroll
            for (int hh = 0; hh < 2; hh++) {
                float* cp = C + (size_t)(r0 + hh * 8) * ldc + n0;
                float2 v = make_float2(acc[mt][nt][hh * 2], acc[mt][nt][hh * 2 + 1]);
                if (EPI == 1) {
                    v.x += bias[n0]; v.y += bias[n0 + 1];
                } else if (EPI == 3) {
                    float2 o = *(float2*)cp;
                    v.x += o.x; v.y += o.y;
                }
                *(float2*)cp = v;
            }
        }
    }
}

// =================== tf32 tensor-core GEMM (xproj, split-K) ================
// Computes partial C_z[m,n] = sum_{k in chunk z} A[m,k]*W[n,k]
#define TBM 128
#define TBN 128
#define TBK 32
#define TROW 36
#define TSTAGE (TBM*TROW)
#define TGEMM_SMEM (4 * TSTAGE * (int)sizeof(float))

__global__ void __launch_bounds__(256, 2)
tgemm_nt_splitk(const float* __restrict__ A, int lda,
                const float* __restrict__ W, int ldw,
                float* __restrict__ Cpart, int ldc,
                int M, int N, int Kchunk)
{
    extern __shared__ float sm[];
    float* As = sm;
    float* Ws = sm + 2 * TSTAGE;

    const int tid  = threadIdx.x;
    const int bm   = blockIdx.y * TBM;
    const int bn   = blockIdx.x * TBN;
    const int kz   = blockIdx.z;
    const int kbase = kz * Kchunk;
    float* C = Cpart + (size_t)kz * M * ldc;

    const int warp = tid >> 5, lane = tid & 31;
    const int wm   = warp & 3;
    const int wn   = warp >> 2;
    const int gid  = lane >> 2, tig = lane & 3;

    float acc[2][8][4];
    #pragma unroll
    for (int i = 0; i < 2; i++)
        #pragma unroll
        for (int j = 0; j < 8; j++)
            #pragma unroll
            for (int q = 0; q < 4; q++) acc[i][j][q] = 0.f;

    auto ldA = [&](int stage, int k0) {
        #pragma unroll
        for (int t = 0; t < 4; t++) {
            int idx = tid + t * 256;
            int r = idx >> 3, kc = (idx & 7) * 4;
            cp_async16g(smem_u32(As + stage * TSTAGE + r * TROW + kc),
                        A + (size_t)(bm + r) * lda + kbase + k0 + kc, 16);
        }
    };
    auto ldW = [&](int stage, int k0) {
        #pragma unroll
        for (int t = 0; t < 4; t++) {
            int idx = tid + t * 256;
            int r = idx >> 3, kc = (idx & 7) * 4;
            int n = bn + r;
            int ok = (n < N);
            cp_async16g(smem_u32(Ws + stage * TSTAGE + r * TROW + kc),
                        W + (size_t)(ok ? n : 0) * ldw + kbase + k0 + kc, ok ? 16 : 0);
        }
    };

    const int nk = Kchunk / TBK;
    ldA(0, 0); ldW(0, 0); cp_commit();

    for (int it = 0; it < nk; it++) {
        int stage = it & 1;
        if (it + 1 < nk) {
            ldA(stage ^ 1, (it + 1) * TBK);
            ldW(stage ^ 1, (it + 1) * TBK);
            cp_commit();
            cp_wait<1>();
        } else {
            cp_wait<0>();
        }
        __syncthreads();

        const uint32_t* Asu = (const uint32_t*)(As + stage * TSTAGE);
        const uint32_t* Wsu = (const uint32_t*)(Ws + stage * TSTAGE);

        #pragma unroll
        for (int kk = 0; kk < TBK; kk += 8) {
            uint32_t af[2][4];
            #pragma unroll
            for (int mt = 0; mt < 2; mt++) {
                int r = wm * 32 + mt * 16 + gid;
                const uint32_t* ap = Asu + r * TROW + kk + tig;
                af[mt][0] = ap[0];
                af[mt][1] = ap[8 * TROW];
                af[mt][2] = ap[4];
                af[mt][3] = ap[8 * TROW + 4];
            }
            uint32_t bfr[8][2];
            #pragma unroll
            for (int nt = 0; nt < 8; nt++) {
                int n = wn * 64 + nt * 8 + gid;
                const uint32_t* bp = Wsu + n * TROW + kk + tig;
                bfr[nt][0] = bp[0];
                bfr[nt][1] = bp[4];
            }
            #pragma unroll
            for (int mt = 0; mt < 2; mt++)
                #pragma unroll
                for (int nt = 0; nt < 8; nt++)
                    mma_tf32(acc[mt][nt], af[mt], bfr[nt]);
        }
        __syncthreads();
    }

    #pragma unroll
    for (int mt = 0; mt < 2; mt++) {
        int r0 = bm + wm * 32 + mt * 16 + gid;
        #pragma unroll
        for (int nt = 0; nt < 8; nt++) {
            int col = bn + wn * 64 + nt * 8 + tig * 2;
            #pragma unroll
            for (int h = 0; h < 2; h++) {
                int m = r0 + h * 8;
                #pragma unroll
                for (int q = 0; q < 2; q++) {
                    int n = col + q;
                    if (n < N) C[(size_t)m * ldc + n] = acc[mt][nt][h * 2 + q];
                }
            }
        }
    }
}

// sum the XPSPLIT partials -> xdbl
__global__ void __launch_bounds__(256)
xp_reduce(const float* __restrict__ p, float* __restrict__ o)
{
    const int i = blockIdx.x * 256 + threadIdx.x;   // 0 .. 2048*96-1
    const int S = Mrows * 96;
    float s = 0.f;
    #pragma unroll
    for (int z = 0; z < XPSPLIT; z++) s += p[(size_t)z * S + i];
    o[i] = s;
}

// =================== fp32 SIMT GEMM (dtproj, accuracy-critical) ============
#define BM 128
#define BN 128
#define BKs 16
#define TM 8
#define TN 8

__global__ void __launch_bounds__(256)
sgemm_softplus(const float* __restrict__ A, int lda,
               const float* __restrict__ W, int ldw,
               float* __restrict__ C, int ldc,
               int K, const float* __restrict__ bias)
{
    __shared__ float As[BKs][BM];
    __shared__ float Ws[BKs][BN];

    const int tid = threadIdx.x;
    const int bm = blockIdx.y * BM;
    const int bn = blockIdx.x * BN;
    const int tx = tid & 15;
    const int ty = tid >> 4;
    const int lr = tid >> 2;
    const int lc = (tid & 3) * 4;

    float acc[TM][TN];
    #pragma unroll
    for (int i = 0; i < TM; i++)
        #pragma unroll
        for (int j = 0; j < TN; j++) acc[i][j] = 0.f;

    for (int k0 = 0; k0 < K; k0 += BKs) {
        #pragma unroll
        for (int h = 0; h < 2; h++) {
            int r = lr + h * 64;
            float4 v = *(const float4*)(A + (size_t)(bm + r) * lda + k0 + lc);
            As[lc + 0][r] = v.x; As[lc + 1][r] = v.y;
            As[lc + 2][r] = v.z; As[lc + 3][r] = v.w;
        }
        #pragma unroll
        for (int h = 0; h < 2; h++) {
            int r = lr + h * 64;
            float4 v = *(const float4*)(W + (size_t)(bn + r) * ldw + k0 + lc);
            Ws[lc + 0][r] = v.x; Ws[lc + 1][r] = v.y;
            Ws[lc + 2][r] = v.z; Ws[lc + 3][r] = v.w;
        }
        __syncthreads();

        #pragma unroll
        for (int k = 0; k < BKs; k++) {
            float a[TM], b[TN];
            #pragma unroll
            for (int i = 0; i < TM; i++) a[i] = As[k][ty * TM + i];
            #pragma unroll
            for (int j = 0; j < TN; j++) b[j] = Ws[k][tx * TN + j];
            #pragma unroll
            for (int i = 0; i < TM; i++)
                #pragma unroll
                for (int j = 0; j < TN; j++)
                    acc[i][j] = fmaf(a[i], b[j], acc[i][j]);
        }
        __syncthreads();
    }

    #pragma unroll
    for (int i = 0; i < TM; i++) {
        int m = bm + ty * TM + i;
        #pragma unroll
        for (int j = 0; j < TN; j++) {
            int n = bn + tx * TN + j;
            float s = acc[i][j] + bias[n];
            C[(size_t)m * ldc + n] = fmaxf(s, 0.f) + log1pf(__expf(-fabsf(s)));
        }
    }
}

// ---------------- float -> half conversion ---------------------------------
__global__ void __launch_bounds__(256)
cvt_f2h(const float* __restrict__ s, __half* __restrict__ d, int n)
{
    int i = (blockIdx.x * 256 + threadIdx.x) * 4;
    if (i < n) {
        float4 v = *(const float4*)(s + i);
        __half2* p = (__half2*)(d + i);
        p[0] = __floats2half2_rn(v.x, v.y);
        p[1] = __floats2half2_rn(v.z, v.w);
    }
}

// ---------------- layernorm (fp16 out) -------------------------------------
__global__ void __launch_bounds__(256)
ln_kernel(const float* __restrict__ x, const float* __restrict__ w,
          const float* __restrict__ b, __half* __restrict__ y)
{
    const int row = blockIdx.x;
    const float* xr = x + (size_t)row * DM;
    __half* yr = y + (size_t)row * DM;
    const int tid = threadIdx.x;

    float vals[4];
    float s = 0.f, ss = 0.f;
    #pragma unroll
    for (int i = 0; i < 4; i++) {
        float v = xr[tid + i * 256];
        vals[i] = v;
        s += v; ss += v * v;
    }
    #pragma unroll
    for (int o = 16; o > 0; o >>= 1) {
        s  += __shfl_xor_sync(0xffffffffu, s, o);
        ss += __shfl_xor_sync(0xffffffffu, ss, o);
    }
    __shared__ float sh[16], shh[16];
    int wid = tid >> 5, ln = tid & 31;
    if (ln == 0) { sh[wid] = s; shh[wid] = ss; }
    __syncthreads();
    if (wid == 0) {
        float a = (ln < 8) ? sh[ln] : 0.f;
        float c = (ln < 8) ? shh[ln] : 0.f;
        #pragma unroll
        for (int o = 4; o > 0; o >>= 1) {
            a += __shfl_xor_sync(0xffffffffu, a, o);
            c += __shfl_xor_sync(0xffffffffu, c, o);
        }
        if (ln == 0) { sh[0] = a; shh[0] = c; }
    }
    __syncthreads();
    float mean = sh[0] * (1.f / DM);
    float var  = shh[0] * (1.f / DM) - mean * mean;
    float rstd = rsqrtf(var + 1e-5f);
    #pragma unroll
    for (int i = 0; i < 4; i++) {
        int c = tid + i * 256;
        yr[c] = __float2half((vals[i] - mean) * rstd * w[c] + b[c]);
    }
}

// -------- depthwise causal conv (K=4) + bias + silu ------------------------
__global__ void __launch_bounds__(256)
conv_silu_kernel(const float* __restrict__ xz, const float* __restrict__ cw,
                 const float* __restrict__ cb, float* __restrict__ xm)
{
    const int e  = blockIdx.x * 256 + threadIdx.x;
    const int t0 = blockIdx.y * 8;
    const int b  = blockIdx.z;
    const float4 w = *(const float4*)(cw + e * 4);
    const float bias = cb[e];
    const float* base = xz + (size_t)b * Lseq * (2 * Eexp) + e;

    float v[11];
    #pragma unroll
    for (int i = 0; i < 11; i++) {
        int t = t0 - 3 + i;
        v[i] = (t >= 0) ? base[(size_t)t * (2 * Eexp)] : 0.f;
    }
    #pragma unroll
    for (int j = 0; j < 8; j++) {
        float sacc = bias;
        sacc = fmaf(w.x, v[j],     sacc);
        sacc = fmaf(w.y, v[j + 1], sacc);
        sacc = fmaf(w.z, v[j + 2], sacc);
        sacc = fmaf(w.w, v[j + 3], sacc);
        float sv = sacc / (1.f + __expf(-sacc));
        xm[((size_t)b * Lseq + t0 + j) * Eexp + e] = sv;
    }
}

// ---------------- selective scan + gating (fp16 output) --------------------
__global__ void __launch_bounds__(256)
scan_kernel(const float* __restrict__ u,    const float* __restrict__ dt,
            const float* __restrict__ xdbl, const float* __restrict__ Alog,
            const float* __restrict__ Dp,   const float* __restrict__ xz,
            __half* __restrict__ yg)
{
    const int tid = threadIdx.x;
    const int grp = tid >> 4;
    const int n   = tid & 15;
    const int blk = blockIdx.x;
    const int b   = blk >> 7;
    const int e   = ((blk & 127) << 4) + grp;

    const float A = -__expf(Alog[e * Nst + n]);
    const float D = Dp[e];
    float h = 0.f;
    const size_t rbase = (size_t)b * Lseq;

    float dts = dt[rbase * Eexp + e];
    float us  = u [rbase * Eexp + e];
    float Bn  = xdbl[rbase * 96 + Rrank + n];
    float Cn  = xdbl[rbase * 96 + Rrank + Nst + n];

    for (int t = 0; t < Lseq; t++) {
        float dts_c = dts, us_c = us, Bn_c = Bn, Cn_c = Cn;
        if (t + 1 < Lseq) {
            size_t r = rbase + t + 1;
            dts = dt[r * Eexp + e];
            us  = u [r * Eexp + e];
            Bn  = xdbl[r * 96 + Rrank + n];
            Cn  = xdbl[r * 96 + Rrank + Nst + n];
        }
        float dA = __expf(dts_c * A);
        h = fmaf(dA, h, (dts_c * us_c) * Bn_c);
        float p = h * Cn_c;
        p += __shfl_xor_sync(0xffffffffu, p, 1);
        p += __shfl_xor_sync(0xffffffffu, p, 2);
        p += __shfl_xor_sync(0xffffffffu, p, 4);
        p += __shfl_xor_sync(0xffffffffu, p, 8);
        if (n == 0) {
            size_t r = rbase + t;
            float zv = xz[r * (2 * Eexp) + Eexp + e];
            float yv = fmaf(us_c, D, p);
            yg[r * Eexp + e] = __float2half(yv * (zv / (1.f + __expf(-zv))));
        }
    }
}

// ---------------- host driver ----------------------------------------------
extern "C" void kernel_launch(void* const* d_in, const int* in_sizes, int n_in,
                              void* d_out, int out_size)
{
    const float* x        = (const float*)d_in[0];
    const float* ip_w     = (const float*)d_in[2];
    const float* ip_b     = (const float*)d_in[3];
    const float* ln_w     = (const float*)d_in[4];
    const float* ln_b     = (const float*)d_in[5];
    const float* inproj_w = (const float*)d_in[6];
    const float* conv_w   = (const float*)d_in[7];
    const float* conv_b   = (const float*)d_in[8];
    const float* xproj_w  = (const float*)d_in[9];
    const float* dtproj_w = (const float*)d_in[10];
    const float* dtproj_b = (const float*)d_in[11];
    const float* A_log    = (const float*)d_in[12];
    const float* Dp       = (const float*)d_in[13];
    const float* outproj_w= (const float*)d_in[14];
    const float* fnorm_w  = (const float*)d_in[15];
    const float* fnorm_b  = (const float*)d_in[16];
    const float* op_w     = (const float*)d_in[17];
    const float* op_b     = (const float*)d_in[18];
    float* out = (float*)d_out;

    float *h, *xz, *xm, *xdbl, *xp, *dtb;
    __half *hnh, *ygh, *xh, *wh;
    cudaGetSymbolAddress((void**)&h,    g_h);
    cudaGetSymbolAddress((void**)&xz,   g_xz);
    cudaGetSymbolAddress((void**)&xm,   g_xm);
    cudaGetSymbolAddress((void**)&xdbl, g_xdbl);
    cudaGetSymbolAddress((void**)&xp,   g_xp);
    cudaGetSymbolAddress((void**)&dtb,  g_dt);
    cudaGetSymbolAddress((void**)&hnh,  g_hnh);
    cudaGetSymbolAddress((void**)&ygh,  g_ygh);
    cudaGetSymbolAddress((void**)&xh,   g_xh);
    cudaGetSymbolAddress((void**)&wh,   g_wh);

    cudaFuncSetAttribute(hgemm_nt<0>, cudaFuncAttributeMaxDynamicSharedMemorySize, HSMEM_TOTAL);
    cudaFuncSetAttribute(hgemm_nt<1>, cudaFuncAttributeMaxDynamicSharedMemorySize, HSMEM_TOTAL);
    cudaFuncSetAttribute(hgemm_nt<3>, cudaFuncAttributeMaxDynamicSharedMemorySize, HSMEM_TOTAL);
    cudaFuncSetAttribute(tgemm_nt_splitk, cudaFuncAttributeMaxDynamicSharedMemorySize, TGEMM_SMEM);

    auto cvt = [&](const float* s, __half* d, int n) {
        cvt_f2h<<<(n / 4 + 255) / 256, 256>>>(s, d, n);
    };
    cvt(x,         xh,               Mrows * DIN);
    cvt(ip_w,      wh + WOFF_IP,     DM * DIN);
    cvt(inproj_w,  wh + WOFF_INPROJ, NLAYER * 2 * Eexp * DM);
    cvt(outproj_w, wh + WOFF_OUTPROJ,NLAYER * DM * Eexp);
    cvt(op_w,      wh + WOFF_OP,     DIN * DM);

    // input projection: h = x @ ip_w^T + ip_b   (2048 x 1024 x 512)
    hgemm_nt<1><<<dim3(DM / 128, Mrows / 128), 256, HSMEM_TOTAL>>>(
        xh, DIN, wh + WOFF_IP, DIN, h, DM, DIN, ip_b);

    for (int l = 0; l < NLAYER; l++) {
        ln_kernel<<<Mrows, 256>>>(h, ln_w + l * DM, ln_b + l * DM, hnh);

        // xz = hn @ inproj^T   (2048 x 4096 x 1024)
        hgemm_nt<0><<<dim3(2 * Eexp / 128, Mrows / 128), 256, HSMEM_TOTAL>>>(
            hnh, DM, wh + WOFF_INPROJ + (size_t)l * 2 * Eexp * DM, DM,
            xz, 2 * Eexp, DM, nullptr);

        conv_silu_kernel<<<dim3(Eexp / 256, Lseq / 8, Bsz), 256>>>(
            xz, conv_w + l * Eexp * Kconv, conv_b + l * Eexp, xm);

        // x_dbl = xm @ xproj^T  (2048 x 96 x 2048), tf32 split-K x8
        tgemm_nt_splitk<<<dim3(1, Mrows / TBM, XPSPLIT), 256, TGEMM_SMEM>>>(
            xm, Eexp, xproj_w + (size_t)l * 96 * Eexp, Eexp,
            xp, 96, Mrows, 96, Eexp / XPSPLIT);
        xp_reduce<<<(Mrows * 96) / 256, 256>>>(xp, xdbl);

        // dt = softplus(x_dbl[:, :R] @ dtproj^T + dtproj_b) -- fp32
        sgemm_softplus<<<dim3(Eexp / BN, Mrows / BM), 256>>>(
            xdbl, 96, dtproj_w + (size_t)l * Eexp * Rrank, Rrank,
            dtb, Eexp, Rrank, dtproj_b + l * Eexp);

        scan_kernel<<<256, 256>>>(
            xm, dtb, xdbl, A_log + l * Eexp * Nst, Dp + l * Eexp, xz, ygh);

        // h += yg @ outproj^T   (2048 x 1024 x 2048)
        hgemm_nt<3><<<dim3(DM / 128, Mrows / 128), 256, HSMEM_TOTAL>>>(
            ygh, Eexp, wh + WOFF_OUTPROJ + (size_t)l * DM * Eexp, Eexp,
            h, DM, Eexp, nullptr);
    }

    ln_kernel<<<Mrows, 256>>>(h, fnorm_w, fnorm_b, hnh);
    hgemm_nt<1><<<dim3(DIN / 128, Mrows / 128), 256, HSMEM_TOTAL>>>(
        hnh, DM, wh + WOFF_OP, DM, out, DIN, DM, op_b);
}

// round 9
// speedup vs baseline: 1.4051x; 1.4051x over previous
#include <cuda_runtime.h>
#include <cuda_fp16.h>
#include <cuda_bf16.h>
#include <cstdint>

// Problem constants
#define Bsz 2
#define Lseq 1024
#define DIN 512
#define DM 1024
#define NLAYER 4
#define Eexp 2048
#define Nst 16
#define Rrank 64
#define Kconv 4
#define Mrows (Bsz*Lseq)   // 2048
#define XPSPLIT 8          // split-K factor for xproj

// ---------------- scratch (device globals; no allocation allowed) ----------
__device__ float g_h   [Mrows*DM];
__device__ float g_xz  [Mrows*2*Eexp];
__device__ float g_xm  [Mrows*Eexp];
__device__ float g_xdbl[Mrows*96];
__device__ float g_xp  [XPSPLIT*Mrows*96];   // xproj split-K partials
__device__ float g_dt  [Mrows*Eexp];
__device__ __half g_hnh[Mrows*DM];
__device__ __half g_ygh[Mrows*Eexp];
__device__ __half g_xh [Mrows*DIN];
// converted weights: ip | inproj | outproj | op
#define WOFF_IP      0
#define WOFF_INPROJ  (WOFF_IP + DM*DIN)
#define WOFF_OUTPROJ (WOFF_INPROJ + NLAYER*2*Eexp*DM)
#define WOFF_OP      (WOFF_OUTPROJ + NLAYER*DM*Eexp)
#define WTOTAL       (WOFF_OP + DIN*DM)
__device__ __half g_wh[WTOTAL];

// ---------------- small PTX helpers ----------------------------------------
__device__ __forceinline__ uint32_t smem_u32(const void* p) {
    return (uint32_t)__cvta_generic_to_shared(p);
}
__device__ __forceinline__ void cp_async16(uint32_t dst, const void* src) {
    asm volatile("cp.async.cg.shared.global [%0], [%1], 16;\n"
                 :: "r"(dst), "l"(src));
}
__device__ __forceinline__ void cp_async16g(uint32_t dst, const void* src, int src_bytes) {
    asm volatile("cp.async.cg.shared.global [%0], [%1], 16, %2;\n"
                 :: "r"(dst), "l"(src), "r"(src_bytes));
}
__device__ __forceinline__ void cp_commit() {
    asm volatile("cp.async.commit_group;\n");
}
template<int NPend>
__device__ __forceinline__ void cp_wait() {
    asm volatile("cp.async.wait_group %0;\n" :: "n"(NPend));
}
__device__ __forceinline__ void ldsm_x4(uint32_t& r0, uint32_t& r1,
                                        uint32_t& r2, uint32_t& r3, uint32_t addr) {
    asm volatile("ldmatrix.sync.aligned.m8n8.x4.shared.b16 {%0,%1,%2,%3}, [%4];"
                 : "=r"(r0), "=r"(r1), "=r"(r2), "=r"(r3) : "r"(addr));
}
__device__ __forceinline__ void mma_f16(float* d, const uint32_t* a, const uint32_t* b) {
    asm volatile(
        "mma.sync.aligned.m16n8k16.row.col.f32.f16.f16.f32 "
        "{%0,%1,%2,%3}, {%4,%5,%6,%7}, {%8,%9}, {%0,%1,%2,%3};\n"
        : "+f"(d[0]), "+f"(d[1]), "+f"(d[2]), "+f"(d[3])
        : "r"(a[0]), "r"(a[1]), "r"(a[2]), "r"(a[3]), "r"(b[0]), "r"(b[1]));
}
__device__ __forceinline__ void mma_tf32(float* d, const uint32_t* a, const uint32_t* b) {
    asm volatile(
        "mma.sync.aligned.m16n8k8.row.col.f32.tf32.tf32.f32 "
        "{%0,%1,%2,%3}, {%4,%5,%6,%7}, {%8,%9}, {%0,%1,%2,%3};\n"
        : "+f"(d[0]), "+f"(d[1]), "+f"(d[2]), "+f"(d[3])
        : "r"(a[0]), "r"(a[1]), "r"(a[2]), "r"(a[3]), "r"(b[0]), "r"(b[1]));
}

// =================== fp16 tensor-core NT GEMM (round-7 proven) =============
// C[m,n] = sum_k A[m,k]*W[n,k]; 3-stage cp.async pipeline.
// M,N multiples of 128; K multiple of 32.  EPI: 0 store, 1 +bias, 3 C += acc
#define HRS 40                              // smem row stride in halfs (80 B)
#define HSTAGE_H (128*HRS)
#define HSTAGE_BYTES (HSTAGE_H*2)           // 10240
#define HSTAGES 3
#define HSMEM_TOTAL (2*HSTAGES*HSTAGE_BYTES)  // 61440

template<int EPI>
__global__ void __launch_bounds__(256, 2)
hgemm_nt(const __half* __restrict__ A, int lda,
         const __half* __restrict__ W, int ldw,
         float* __restrict__ C, int ldc,
         int K, const float* __restrict__ bias)
{
    extern __shared__ char smem[];
    __half* As = (__half*)smem;
    __half* Ws = (__half*)(smem + HSTAGES * HSTAGE_BYTES);

    const int tid  = threadIdx.x;
    const int warp = tid >> 5, lane = tid & 31;
    const int bm   = blockIdx.y * 128;
    const int bn   = blockIdx.x * 128;
    const int wm   = warp & 3;
    const int wn   = warp >> 2;
    const int gid  = lane >> 2, tig = lane & 3;

    float acc[2][8][4];
    #pragma unroll
    for (int i = 0; i < 2; i++)
        #pragma unroll
        for (int j = 0; j < 8; j++)
            #pragma unroll
            for (int q = 0; q < 4; q++) acc[i][j][q] = 0.f;

    auto ldA = [&](int s, int kt) {
        #pragma unroll
        for (int t = 0; t < 2; t++) {
            int idx = tid + t * 256;
            int r = idx >> 2, g = idx & 3;
            cp_async16(smem_u32(As + s * HSTAGE_H + r * HRS + g * 8),
                       A + (size_t)(bm + r) * lda + kt * 32 + g * 8);
        }
    };
    auto ldW = [&](int s, int kt) {
        #pragma unroll
        for (int t = 0; t < 2; t++) {
            int idx = tid + t * 256;
            int r = idx >> 2, g = idx & 3;
            cp_async16(smem_u32(Ws + s * HSTAGE_H + r * HRS + g * 8),
                       W + (size_t)(bn + r) * ldw + kt * 32 + g * 8);
        }
    };

    const int nk = K / 32;
    ldA(0, 0); ldW(0, 0); cp_commit();
    ldA(1, 1); ldW(1, 1); cp_commit();

    const int arow = wm * 32 + (lane & 15);
    const int acol = (lane >> 4) << 3;
    const int brow = wn * 64 + (lane & 7) + ((lane & 16) >> 1);
    const int bcol = lane & 8;

    for (int it = 0; it < nk; it++) {
        const int s = it % HSTAGES;
        if (it == nk - 1) cp_wait<0>(); else cp_wait<1>();
        __syncthreads();

        const __half* Asb = As + s * HSTAGE_H;
        const __half* Wsb = Ws + s * HSTAGE_H;

        #pragma unroll
        for (int kk = 0; kk < 32; kk += 16) {
            uint32_t af[2][4];
            #pragma unroll
            for (int mt = 0; mt < 2; mt++)
                ldsm_x4(af[mt][0], af[mt][1], af[mt][2], af[mt][3],
                        smem_u32(Asb + (arow + mt * 16) * HRS + kk + acol));
            uint32_t bf[8][2];
            #pragma unroll
            for (int ntp = 0; ntp < 4; ntp++)
                ldsm_x4(bf[ntp * 2][0], bf[ntp * 2][1],
                        bf[ntp * 2 + 1][0], bf[ntp * 2 + 1][1],
                        smem_u32(Wsb + (brow + ntp * 16) * HRS + kk + bcol));
            #pragma unroll
            for (int mt = 0; mt < 2; mt++)
                #pragma unroll
                for (int nt = 0; nt < 8; nt++)
                    mma_f16(acc[mt][nt], af[mt], bf[nt]);
        }

        if (it + 2 < nk) {
            const int s2 = (it + 2) % HSTAGES;
            ldA(s2, it + 2); ldW(s2, it + 2); cp_commit();
        }
    }

    #pragma unroll
    for (int mt = 0; mt < 2; mt++) {
        int r0 = bm + wm * 32 + mt * 16 + gid;
        #pragma unroll
        for (int nt = 0; nt < 8; nt++) {
            int n0 = bn + wn * 64 + nt * 8 + tig * 2;
            #pragma unroll
            for (int hh = 0; hh < 2; hh++) {
                float* cp = C + (size_t)(r0 + hh * 8) * ldc + n0;
                float2 v = make_float2(acc[mt][nt][hh * 2], acc[mt][nt][hh * 2 + 1]);
                if (EPI == 1) {
                    v.x += bias[n0]; v.y += bias[n0 + 1];
                } else if (EPI == 3) {
                    float2 o = *(float2*)cp;
                    v.x += o.x; v.y += o.y;
                }
                *(float2*)cp = v;
            }
        }
    }
}

// =================== tf32 tensor-core GEMM (xproj, split-K) ================
#define TBM 128
#define TBN 128
#define TBK 32
#define TROW 36
#define TSTAGE (TBM*TROW)
#define TGEMM_SMEM (4 * TSTAGE * (int)sizeof(float))

__global__ void __launch_bounds__(256, 2)
tgemm_nt_splitk(const float* __restrict__ A, int lda,
                const float* __restrict__ W, int ldw,
                float* __restrict__ Cpart, int ldc,
                int M, int N, int Kchunk)
{
    extern __shared__ float sm[];
    float* As = sm;
    float* Ws = sm + 2 * TSTAGE;

    const int tid  = threadIdx.x;
    const int bm   = blockIdx.y * TBM;
    const int bn   = blockIdx.x * TBN;
    const int kz   = blockIdx.z;
    const int kbase = kz * Kchunk;
    float* C = Cpart + (size_t)kz * M * ldc;

    const int warp = tid >> 5, lane = tid & 31;
    const int wm   = warp & 3;
    const int wn   = warp >> 2;
    const int gid  = lane >> 2, tig = lane & 3;

    float acc[2][8][4];
    #pragma unroll
    for (int i = 0; i < 2; i++)
        #pragma unroll
        for (int j = 0; j < 8; j++)
            #pragma unroll
            for (int q = 0; q < 4; q++) acc[i][j][q] = 0.f;

    auto ldA = [&](int stage, int k0) {
        #pragma unroll
        for (int t = 0; t < 4; t++) {
            int idx = tid + t * 256;
            int r = idx >> 3, kc = (idx & 7) * 4;
            cp_async16g(smem_u32(As + stage * TSTAGE + r * TROW + kc),
                        A + (size_t)(bm + r) * lda + kbase + k0 + kc, 16);
        }
    };
    auto ldW = [&](int stage, int k0) {
        #pragma unroll
        for (int t = 0; t < 4; t++) {
            int idx = tid + t * 256;
            int r = idx >> 3, kc = (idx & 7) * 4;
            int n = bn + r;
            int ok = (n < N);
            cp_async16g(smem_u32(Ws + stage * TSTAGE + r * TROW + kc),
                        W + (size_t)(ok ? n : 0) * ldw + kbase + k0 + kc, ok ? 16 : 0);
        }
    };

    const int nk = Kchunk / TBK;
    ldA(0, 0); ldW(0, 0); cp_commit();

    for (int it = 0; it < nk; it++) {
        int stage = it & 1;
        if (it + 1 < nk) {
            ldA(stage ^ 1, (it + 1) * TBK);
            ldW(stage ^ 1, (it + 1) * TBK);
            cp_commit();
            cp_wait<1>();
        } else {
            cp_wait<0>();
        }
        __syncthreads();

        const uint32_t* Asu = (const uint32_t*)(As + stage * TSTAGE);
        const uint32_t* Wsu = (const uint32_t*)(Ws + stage * TSTAGE);

        #pragma unroll
        for (int kk = 0; kk < TBK; kk += 8) {
            uint32_t af[2][4];
            #pragma unroll
            for (int mt = 0; mt < 2; mt++) {
                int r = wm * 32 + mt * 16 + gid;
                const uint32_t* ap = Asu + r * TROW + kk + tig;
                af[mt][0] = ap[0];
                af[mt][1] = ap[8 * TROW];
                af[mt][2] = ap[4];
                af[mt][3] = ap[8 * TROW + 4];
            }
            uint32_t bfr[8][2];
            #pragma unroll
            for (int nt = 0; nt < 8; nt++) {
                int n = wn * 64 + nt * 8 + gid;
                const uint32_t* bp = Wsu + n * TROW + kk + tig;
                bfr[nt][0] = bp[0];
                bfr[nt][1] = bp[4];
            }
            #pragma unroll
            for (int mt = 0; mt < 2; mt++)
                #pragma unroll
                for (int nt = 0; nt < 8; nt++)
                    mma_tf32(acc[mt][nt], af[mt], bfr[nt]);
        }
        __syncthreads();
    }

    #pragma unroll
    for (int mt = 0; mt < 2; mt++) {
        int r0 = bm + wm * 32 + mt * 16 + gid;
        #pragma unroll
        for (int nt = 0; nt < 8; nt++) {
            int col = bn + wn * 64 + nt * 8 + tig * 2;
            #pragma unroll
            for (int h = 0; h < 2; h++) {
                int m = r0 + h * 8;
                #pragma unroll
                for (int q = 0; q < 2; q++) {
                    int n = col + q;
                    if (n < N) C[(size_t)m * ldc + n] = acc[mt][nt][h * 2 + q];
                }
            }
        }
    }
}

// sum the XPSPLIT partials -> xdbl
__global__ void __launch_bounds__(256)
xp_reduce(const float* __restrict__ p, float* __restrict__ o)
{
    const int i = blockIdx.x * 256 + threadIdx.x;
    const int S = Mrows * 96;
    float s = 0.f;
    #pragma unroll
    for (int z = 0; z < XPSPLIT; z++) s += p[(size_t)z * S + i];
    o[i] = s;
}

// =================== fp32 SIMT GEMM (dtproj, accuracy-critical) ============
#define BM 128
#define BN 128
#define BKs 16
#define TM 8
#define TN 8

__global__ void __launch_bounds__(256)
sgemm_softplus(const float* __restrict__ A, int lda,
               const float* __restrict__ W, int ldw,
               float* __restrict__ C, int ldc,
               int K, const float* __restrict__ bias)
{
    __shared__ float As[BKs][BM];
    __shared__ float Ws[BKs][BN];

    const int tid = threadIdx.x;
    const int bm = blockIdx.y * BM;
    const int bn = blockIdx.x * BN;
    const int tx = tid & 15;
    const int ty = tid >> 4;
    const int lr = tid >> 2;
    const int lc = (tid & 3) * 4;

    float acc[TM][TN];
    #pragma unroll
    for (int i = 0; i < TM; i++)
        #pragma unroll
        for (int j = 0; j < TN; j++) acc[i][j] = 0.f;

    for (int k0 = 0; k0 < K; k0 += BKs) {
        #pragma unroll
        for (int h = 0; h < 2; h++) {
            int r = lr + h * 64;
            float4 v = *(const float4*)(A + (size_t)(bm + r) * lda + k0 + lc);
            As[lc + 0][r] = v.x; As[lc + 1][r] = v.y;
            As[lc + 2][r] = v.z; As[lc + 3][r] = v.w;
        }
        #pragma unroll
        for (int h = 0; h < 2; h++) {
            int r = lr + h * 64;
            float4 v = *(const float4*)(W + (size_t)(bn + r) * ldw + k0 + lc);
            Ws[lc + 0][r] = v.x; Ws[lc + 1][r] = v.y;
            Ws[lc + 2][r] = v.z; Ws[lc + 3][r] = v.w;
        }
        __syncthreads();

        #pragma unroll
        for (int k = 0; k < BKs; k++) {
            float a[TM], b[TN];
            #pragma unroll
            for (int i = 0; i < TM; i++) a[i] = As[k][ty * TM + i];
            #pragma unroll
            for (int j = 0; j < TN; j++) b[j] = Ws[k][tx * TN + j];
            #pragma unroll
            for (int i = 0; i < TM; i++)
                #pragma unroll
                for (int j = 0; j < TN; j++)
                    acc[i][j] = fmaf(a[i], b[j], acc[i][j]);
        }
        __syncthreads();
    }

    #pragma unroll
    for (int i = 0; i < TM; i++) {
        int m = bm + ty * TM + i;
        #pragma unroll
        for (int j = 0; j < TN; j++) {
            int n = bn + tx * TN + j;
            float s = acc[i][j] + bias[n];
            C[(size_t)m * ldc + n] = fmaxf(s, 0.f) + log1pf(__expf(-fabsf(s)));
        }
    }
}

// ---------------- float -> half conversion ---------------------------------
__global__ void __launch_bounds__(256)
cvt_f2h(const float* __restrict__ s, __half* __restrict__ d, int n)
{
    int i = (blockIdx.x * 256 + threadIdx.x) * 4;
    if (i < n) {
        float4 v = *(const float4*)(s + i);
        __half2* p = (__half2*)(d + i);
        p[0] = __floats2half2_rn(v.x, v.y);
        p[1] = __floats2half2_rn(v.z, v.w);
    }
}

// ---------------- layernorm (fp16 out) -------------------------------------
__global__ void __launch_bounds__(256)
ln_kernel(const float* __restrict__ x, const float* __restrict__ w,
          const float* __restrict__ b, __half* __restrict__ y)
{
    const int row = blockIdx.x;
    const float* xr = x + (size_t)row * DM;
    __half* yr = y + (size_t)row * DM;
    const int tid = threadIdx.x;

    float vals[4];
    float s = 0.f, ss = 0.f;
    #pragma unroll
    for (int i = 0; i < 4; i++) {
        float v = xr[tid + i * 256];
        vals[i] = v;
        s += v; ss += v * v;
    }
    #pragma unroll
    for (int o = 16; o > 0; o >>= 1) {
        s  += __shfl_xor_sync(0xffffffffu, s, o);
        ss += __shfl_xor_sync(0xffffffffu, ss, o);
    }
    __shared__ float sh[16], shh[16];
    int wid = tid >> 5, ln = tid & 31;
    if (ln == 0) { sh[wid] = s; shh[wid] = ss; }
    __syncthreads();
    if (wid == 0) {
        float a = (ln < 8) ? sh[ln] : 0.f;
        float c = (ln < 8) ? shh[ln] : 0.f;
        #pragma unroll
        for (int o = 4; o > 0; o >>= 1) {
            a += __shfl_xor_sync(0xffffffffu, a, o);
            c += __shfl_xor_sync(0xffffffffu, c, o);
        }
        if (ln == 0) { sh[0] = a; shh[0] = c; }
    }
    __syncthreads();
    float mean = sh[0] * (1.f / DM);
    float var  = shh[0] * (1.f / DM) - mean * mean;
    float rstd = rsqrtf(var + 1e-5f);
    #pragma unroll
    for (int i = 0; i < 4; i++) {
        int c = tid + i * 256;
        yr[c] = __float2half((vals[i] - mean) * rstd * w[c] + b[c]);
    }
}

// -------- depthwise causal conv (K=4) + bias + silu ------------------------
__global__ void __launch_bounds__(256)
conv_silu_kernel(const float* __restrict__ xz, const float* __restrict__ cw,
                 const float* __restrict__ cb, float* __restrict__ xm)
{
    const int e  = blockIdx.x * 256 + threadIdx.x;
    const int t0 = blockIdx.y * 8;
    const int b  = blockIdx.z;
    const float4 w = *(const float4*)(cw + e * 4);
    const float bias = cb[e];
    const float* base = xz + (size_t)b * Lseq * (2 * Eexp) + e;

    float v[11];
    #pragma unroll
    for (int i = 0; i < 11; i++) {
        int t = t0 - 3 + i;
        v[i] = (t >= 0) ? base[(size_t)t * (2 * Eexp)] : 0.f;
    }
    #pragma unroll
    for (int j = 0; j < 8; j++) {
        float sacc = bias;
        sacc = fmaf(w.x, v[j],     sacc);
        sacc = fmaf(w.y, v[j + 1], sacc);
        sacc = fmaf(w.z, v[j + 2], sacc);
        sacc = fmaf(w.w, v[j + 3], sacc);
        float sv = sacc / (1.f + __expf(-sacc));
        xm[((size_t)b * Lseq + t0 + j) * Eexp + e] = sv;
    }
}

// ---------------- selective scan + gating (fp16 output) --------------------
__global__ void __launch_bounds__(256)
scan_kernel(const float* __restrict__ u,    const float* __restrict__ dt,
            const float* __restrict__ xdbl, const float* __restrict__ Alog,
            const float* __restrict__ Dp,   const float* __restrict__ xz,
            __half* __restrict__ yg)
{
    const int tid = threadIdx.x;
    const int grp = tid >> 4;
    const int n   = tid & 15;
    const int blk = blockIdx.x;
    const int b   = blk >> 7;
    const int e   = ((blk & 127) << 4) + grp;

    const float A = -__expf(Alog[e * Nst + n]);
    const float D = Dp[e];
    float h = 0.f;
    const size_t rbase = (size_t)b * Lseq;

    float dts = dt[rbase * Eexp + e];
    float us  = u [rbase * Eexp + e];
    float Bn  = xdbl[rbase * 96 + Rrank + n];
    float Cn  = xdbl[rbase * 96 + Rrank + Nst + n];

    for (int t = 0; t < Lseq; t++) {
        float dts_c = dts, us_c = us, Bn_c = Bn, Cn_c = Cn;
        if (t + 1 < Lseq) {
            size_t r = rbase + t + 1;
            dts = dt[r * Eexp + e];
            us  = u [r * Eexp + e];
            Bn  = xdbl[r * 96 + Rrank + n];
            Cn  = xdbl[r * 96 + Rrank + Nst + n];
        }
        float dA = __expf(dts_c * A);
        h = fmaf(dA, h, (dts_c * us_c) * Bn_c);
        float p = h * Cn_c;
        p += __shfl_xor_sync(0xffffffffu, p, 1);
        p += __shfl_xor_sync(0xffffffffu, p, 2);
        p += __shfl_xor_sync(0xffffffffu, p, 4);
        p += __shfl_xor_sync(0xffffffffu, p, 8);
        if (n == 0) {
            size_t r = rbase + t;
            float zv = xz[r * (2 * Eexp) + Eexp + e];
            float yv = fmaf(us_c, D, p);
            yg[r * Eexp + e] = __float2half(yv * (zv / (1.f + __expf(-zv))));
        }
    }
}

// ---------------- host driver ----------------------------------------------
extern "C" void kernel_launch(void* const* d_in, const int* in_sizes, int n_in,
                              void* d_out, int out_size)
{
    const float* x        = (const float*)d_in[0];
    const float* ip_w     = (const float*)d_in[2];
    const float* ip_b     = (const float*)d_in[3];
    const float* ln_w     = (const float*)d_in[4];
    const float* ln_b     = (const float*)d_in[5];
    const float* inproj_w = (const float*)d_in[6];
    const float* conv_w   = (const float*)d_in[7];
    const float* conv_b   = (const float*)d_in[8];
    const float* xproj_w  = (const float*)d_in[9];
    const float* dtproj_w = (const float*)d_in[10];
    const float* dtproj_b = (const float*)d_in[11];
    const float* A_log    = (const float*)d_in[12];
    const float* Dp       = (const float*)d_in[13];
    const float* outproj_w= (const float*)d_in[14];
    const float* fnorm_w  = (const float*)d_in[15];
    const float* fnorm_b  = (const float*)d_in[16];
    const float* op_w     = (const float*)d_in[17];
    const float* op_b     = (const float*)d_in[18];
    float* out = (float*)d_out;

    float *h, *xz, *xm, *xdbl, *xp, *dtb;
    __half *hnh, *ygh, *xh, *wh;
    cudaGetSymbolAddress((void**)&h,    g_h);
    cudaGetSymbolAddress((void**)&xz,   g_xz);
    cudaGetSymbolAddress((void**)&xm,   g_xm);
    cudaGetSymbolAddress((void**)&xdbl, g_xdbl);
    cudaGetSymbolAddress((void**)&xp,   g_xp);
    cudaGetSymbolAddress((void**)&dtb,  g_dt);
    cudaGetSymbolAddress((void**)&hnh,  g_hnh);
    cudaGetSymbolAddress((void**)&ygh,  g_ygh);
    cudaGetSymbolAddress((void**)&xh,   g_xh);
    cudaGetSymbolAddress((void**)&wh,   g_wh);

    cudaFuncSetAttribute(hgemm_nt<0>, cudaFuncAttributeMaxDynamicSharedMemorySize, HSMEM_TOTAL);
    cudaFuncSetAttribute(hgemm_nt<1>, cudaFuncAttributeMaxDynamicSharedMemorySize, HSMEM_TOTAL);
    cudaFuncSetAttribute(hgemm_nt<3>, cudaFuncAttributeMaxDynamicSharedMemorySize, HSMEM_TOTAL);
    cudaFuncSetAttribute(tgemm_nt_splitk, cudaFuncAttributeMaxDynamicSharedMemorySize, TGEMM_SMEM);

    auto cvt = [&](const float* s, __half* d, int n) {
        cvt_f2h<<<(n / 4 + 255) / 256, 256>>>(s, d, n);
    };
    cvt(x,         xh,               Mrows * DIN);
    cvt(ip_w,      wh + WOFF_IP,     DM * DIN);
    cvt(inproj_w,  wh + WOFF_INPROJ, NLAYER * 2 * Eexp * DM);
    cvt(outproj_w, wh + WOFF_OUTPROJ,NLAYER * DM * Eexp);
    cvt(op_w,      wh + WOFF_OP,     DIN * DM);

    // input projection: h = x @ ip_w^T + ip_b   (2048 x 1024 x 512)
    hgemm_nt<1><<<dim3(DM / 128, Mrows / 128), 256, HSMEM_TOTAL>>>(
        xh, DIN, wh + WOFF_IP, DIN, h, DM, DIN, ip_b);

    for (int l = 0; l < NLAYER; l++) {
        ln_kernel<<<Mrows, 256>>>(h, ln_w + l * DM, ln_b + l * DM, hnh);

        // xz = hn @ inproj^T   (2048 x 4096 x 1024)
        hgemm_nt<0><<<dim3(2 * Eexp / 128, Mrows / 128), 256, HSMEM_TOTAL>>>(
            hnh, DM, wh + WOFF_INPROJ + (size_t)l * 2 * Eexp * DM, DM,
            xz, 2 * Eexp, DM, nullptr);

        conv_silu_kernel<<<dim3(Eexp / 256, Lseq / 8, Bsz), 256>>>(
            xz, conv_w + l * Eexp * Kconv, conv_b + l * Eexp, xm);

        // x_dbl = xm @ xproj^T  (2048 x 96 x 2048), tf32 split-K x8
        tgemm_nt_splitk<<<dim3(1, Mrows / TBM, XPSPLIT), 256, TGEMM_SMEM>>>(
            xm, Eexp, xproj_w + (size_t)l * 96 * Eexp, Eexp,
            xp, 96, Mrows, 96, Eexp / XPSPLIT);
        xp_reduce<<<(Mrows * 96) / 256, 256>>>(xp, xdbl);

        // dt = softplus(x_dbl[:, :R] @ dtproj^T + dtproj_b) -- fp32
        sgemm_softplus<<<dim3(Eexp / BN, Mrows / BM), 256>>>(
            xdbl, 96, dtproj_w + (size_t)l * Eexp * Rrank, Rrank,
            dtb, Eexp, Rrank, dtproj_b + l * Eexp);

        scan_kernel<<<256, 256>>>(
            xm, dtb, xdbl, A_log + l * Eexp * Nst, Dp + l * Eexp, xz, ygh);

        // h += yg @ outproj^T   (2048 x 1024 x 2048)
        hgemm_nt<3><<<dim3(DM / 128, Mrows / 128), 256, HSMEM_TOTAL>>>(
            ygh, Eexp, wh + WOFF_OUTPROJ + (size_t)l * DM * Eexp, Eexp,
            h, DM, Eexp, nullptr);
    }

    ln_kernel<<<Mrows, 256>>>(h, fnorm_w, fnorm_b, hnh);
    hgemm_nt<1><<<dim3(DIN / 128, Mrows / 128), 256, HSMEM_TOTAL>>>(
        hnh, DM, wh + WOFF_OP, DM, out, DIN, DM, op_b);
}

// round 14
// speedup vs baseline: 1.4241x; 1.0136x over previous
#include <cuda_runtime.h>
#include <cuda_fp16.h>
#include <cuda_bf16.h>
#include <cstdint>

// Problem constants
#define Bsz 2
#define Lseq 1024
#define DIN 512
#define DM 1024
#define NLAYER 4
#define Eexp 2048
#define Nst 16
#define Rrank 64
#define Kconv 4
#define Mrows (Bsz*Lseq)   // 2048
#define XPSPLIT 8          // split-K factor for xproj

// ---------------- scratch (device globals; no allocation allowed) ----------
__device__ float g_h   [Mrows*DM];
__device__ float g_xz  [Mrows*2*Eexp];
__device__ float g_xm  [Mrows*Eexp];
__device__ float g_xdbl[Mrows*96];
__device__ float g_xp  [XPSPLIT*Mrows*96];   // xproj split-K partials
__device__ float g_part[4*Mrows*DIN];        // split-K partials (= 2*Mrows*DM)
__device__ float g_dt  [Mrows*Eexp];
__device__ __half g_hnh[Mrows*DM];
__device__ __half g_ygh[Mrows*Eexp];
__device__ __half g_xh [Mrows*DIN];
// converted weights: ip | inproj | outproj | op
#define WOFF_IP      0
#define WOFF_INPROJ  (WOFF_IP + DM*DIN)
#define WOFF_OUTPROJ (WOFF_INPROJ + NLAYER*2*Eexp*DM)
#define WOFF_OP      (WOFF_OUTPROJ + NLAYER*DM*Eexp)
#define WTOTAL       (WOFF_OP + DIN*DM)
__device__ __half g_wh[WTOTAL];

// ---------------- small PTX helpers ----------------------------------------
__device__ __forceinline__ uint32_t smem_u32(const void* p) {
    return (uint32_t)__cvta_generic_to_shared(p);
}
__device__ __forceinline__ void cp_async16(uint32_t dst, const void* src) {
    asm volatile("cp.async.cg.shared.global [%0], [%1], 16;\n"
                 :: "r"(dst), "l"(src));
}
__device__ __forceinline__ void cp_async16g(uint32_t dst, const void* src, int src_bytes) {
    asm volatile("cp.async.cg.shared.global [%0], [%1], 16, %2;\n"
                 :: "r"(dst), "l"(src), "r"(src_bytes));
}
__device__ __forceinline__ void cp_commit() {
    asm volatile("cp.async.commit_group;\n");
}
template<int NPend>
__device__ __forceinline__ void cp_wait() {
    asm volatile("cp.async.wait_group %0;\n" :: "n"(NPend));
}
__device__ __forceinline__ void ldsm_x4(uint32_t& r0, uint32_t& r1,
                                        uint32_t& r2, uint32_t& r3, uint32_t addr) {
    asm volatile("ldmatrix.sync.aligned.m8n8.x4.shared.b16 {%0,%1,%2,%3}, [%4];"
                 : "=r"(r0), "=r"(r1), "=r"(r2), "=r"(r3) : "r"(addr));
}
__device__ __forceinline__ void mma_f16(float* d, const uint32_t* a, const uint32_t* b) {
    asm volatile(
        "mma.sync.aligned.m16n8k16.row.col.f32.f16.f16.f32 "
        "{%0,%1,%2,%3}, {%4,%5,%6,%7}, {%8,%9}, {%0,%1,%2,%3};\n"
        : "+f"(d[0]), "+f"(d[1]), "+f"(d[2]), "+f"(d[3])
        : "r"(a[0]), "r"(a[1]), "r"(a[2]), "r"(a[3]), "r"(b[0]), "r"(b[1]));
}
__device__ __forceinline__ void mma_tf32(float* d, const uint32_t* a, const uint32_t* b) {
    asm volatile(
        "mma.sync.aligned.m16n8k8.row.col.f32.tf32.tf32.f32 "
        "{%0,%1,%2,%3}, {%4,%5,%6,%7}, {%8,%9}, {%0,%1,%2,%3};\n"
        : "+f"(d[0]), "+f"(d[1]), "+f"(d[2]), "+f"(d[3])
        : "r"(a[0]), "r"(a[1]), "r"(a[2]), "r"(a[3]), "r"(b[0]), "r"(b[1]));
}

// =================== fp16 tensor-core NT GEMM (round-7 core) ===============
// C[m,n] = sum_k A[m,k]*W[n,k]; 3-stage cp.async pipeline.
// Split-K via blockIdx.z: chunk kz covers K columns [kz*K, (kz+1)*K),
// output goes to C + kz*M*ldc.  EPI: 0 store, 1 +bias, 3 C += acc
#define HRS 40                              // smem row stride in halfs (80 B)
#define HSTAGE_H (128*HRS)
#define HSTAGE_BYTES (HSTAGE_H*2)           // 10240
#define HSTAGES 3
#define HSMEM_TOTAL (2*HSTAGES*HSTAGE_BYTES)  // 61440

template<int EPI>
__global__ void __launch_bounds__(256, 2)
hgemm_nt(const __half* __restrict__ A, int lda,
         const __half* __restrict__ W, int ldw,
         float* __restrict__ C, int ldc,
         int M, int K, const float* __restrict__ bias)
{
    extern __shared__ char smem[];
    __half* As = (__half*)smem;
    __half* Ws = (__half*)(smem + HSTAGES * HSTAGE_BYTES);

    const int tid  = threadIdx.x;
    const int warp = tid >> 5, lane = tid & 31;
    const int bm   = blockIdx.y * 128;
    const int bn   = blockIdx.x * 128;
    const int koff = blockIdx.z * K;
    C += (size_t)blockIdx.z * M * ldc;
    const int wm   = warp & 3;
    const int wn   = warp >> 2;
    const int gid  = lane >> 2, tig = lane & 3;

    float acc[2][8][4];
    #pragma unroll
    for (int i = 0; i < 2; i++)
        #pragma unroll
        for (int j = 0; j < 8; j++)
            #pragma unroll
            for (int q = 0; q < 4; q++) acc[i][j][q] = 0.f;

    auto ldA = [&](int s, int kt) {
        #pragma unroll
        for (int t = 0; t < 2; t++) {
            int idx = tid + t * 256;
            int r = idx >> 2, g = idx & 3;
            cp_async16(smem_u32(As + s * HSTAGE_H + r * HRS + g * 8),
                       A + (size_t)(bm + r) * lda + koff + kt * 32 + g * 8);
        }
    };
    auto ldW = [&](int s, int kt) {
        #pragma unroll
        for (int t = 0; t < 2; t++) {
            int idx = tid + t * 256;
            int r = idx >> 2, g = idx & 3;
            cp_async16(smem_u32(Ws + s * HSTAGE_H + r * HRS + g * 8),
                       W + (size_t)(bn + r) * ldw + koff + kt * 32 + g * 8);
        }
    };

    const int nk = K / 32;
    ldA(0, 0); ldW(0, 0); cp_commit();
    ldA(1, 1); ldW(1, 1); cp_commit();

    const int arow = wm * 32 + (lane & 15);
    const int acol = (lane >> 4) << 3;
    const int brow = wn * 64 + (lane & 7) + ((lane & 16) >> 1);
    const int bcol = lane & 8;

    for (int it = 0; it < nk; it++) {
        const int s = it % HSTAGES;
        if (it == nk - 1) cp_wait<0>(); else cp_wait<1>();
        __syncthreads();

        const __half* Asb = As + s * HSTAGE_H;
        const __half* Wsb = Ws + s * HSTAGE_H;

        #pragma unroll
        for (int kk = 0; kk < 32; kk += 16) {
            uint32_t af[2][4];
            #pragma unroll
            for (int mt = 0; mt < 2; mt++)
                ldsm_x4(af[mt][0], af[mt][1], af[mt][2], af[mt][3],
                        smem_u32(Asb + (arow + mt * 16) * HRS + kk + acol));
            uint32_t bf[8][2];
            #pragma unroll
            for (int ntp = 0; ntp < 4; ntp++)
                ldsm_x4(bf[ntp * 2][0], bf[ntp * 2][1],
                        bf[ntp * 2 + 1][0], bf[ntp * 2 + 1][1],
                        smem_u32(Wsb + (brow + ntp * 16) * HRS + kk + bcol));
            #pragma unroll
            for (int mt = 0; mt < 2; mt++)
                #pragma unroll
                for (int nt = 0; nt < 8; nt++)
                    mma_f16(acc[mt][nt], af[mt], bf[nt]);
        }

        if (it + 2 < nk) {
            const int s2 = (it + 2) % HSTAGES;
            ldA(s2, it + 2); ldW(s2, it + 2); cp_commit();
        }
    }

    #pragma unroll
    for (int mt = 0; mt < 2; mt++) {
        int r0 = bm + wm * 32 + mt * 16 + gid;
        #pragma unroll
        for (int nt = 0; nt < 8; nt++) {
            int n0 = bn + wn * 64 + nt * 8 + tig * 2;
            #pragma unroll
            for (int hh = 0; hh < 2; hh++) {
                float* cp = C + (size_t)(r0 + hh * 8) * ldc + n0;
                float2 v = make_float2(acc[mt][nt][hh * 2], acc[mt][nt][hh * 2 + 1]);
                if (EPI == 1) {
                    v.x += bias[n0]; v.y += bias[n0 + 1];
                } else if (EPI == 3) {
                    float2 o = *(float2*)cp;
                    v.x += o.x; v.y += o.y;
                }
                *(float2*)cp = v;
            }
        }
    }
}

// -------- split-K reduce: C = sum_z part[z] (+bias | += ) -------------------
// MODE 0: C = sum + bias[n];  MODE 1: C += sum
template<int S, int MODE>
__global__ void __launch_bounds__(256)
reduce_k(const float* __restrict__ p, const float* __restrict__ bias,
         float* __restrict__ C, int N, int total)
{
    int i = (blockIdx.x * 256 + threadIdx.x) * 4;
    if (i >= total) return;
    float4 s = *(const float4*)(p + i);
    #pragma unroll
    for (int z = 1; z < S; z++) {
        float4 t = *(const float4*)(p + (size_t)z * total + i);
        s.x += t.x; s.y += t.y; s.z += t.z; s.w += t.w;
    }
    if (MODE == 0) {
        const float4 b = *(const float4*)(bias + (i % N));
        s.x += b.x; s.y += b.y; s.z += b.z; s.w += b.w;
        *(float4*)(C + i) = s;
    } else {
        float4 o = *(const float4*)(C + i);
        s.x += o.x; s.y += o.y; s.z += o.z; s.w += o.w;
        *(float4*)(C + i) = s;
    }
}

// =================== tf32 tensor-core GEMM (xproj, split-K) ================
#define TBM 128
#define TBN 128
#define TBK 32
#define TROW 36
#define TSTAGE (TBM*TROW)
#define TGEMM_SMEM (4 * TSTAGE * (int)sizeof(float))

__global__ void __launch_bounds__(256, 2)
tgemm_nt_splitk(const float* __restrict__ A, int lda,
                const float* __restrict__ W, int ldw,
                float* __restrict__ Cpart, int ldc,
                int M, int N, int Kchunk)
{
    extern __shared__ float sm[];
    float* As = sm;
    float* Ws = sm + 2 * TSTAGE;

    const int tid  = threadIdx.x;
    const int bm   = blockIdx.y * TBM;
    const int bn   = blockIdx.x * TBN;
    const int kz   = blockIdx.z;
    const int kbase = kz * Kchunk;
    float* C = Cpart + (size_t)kz * M * ldc;

    const int warp = tid >> 5, lane = tid & 31;
    const int wm   = warp & 3;
    const int wn   = warp >> 2;
    const int gid  = lane >> 2, tig = lane & 3;

    float acc[2][8][4];
    #pragma unroll
    for (int i = 0; i < 2; i++)
        #pragma unroll
        for (int j = 0; j < 8; j++)
            #pragma unroll
            for (int q = 0; q < 4; q++) acc[i][j][q] = 0.f;

    auto ldA = [&](int stage, int k0) {
        #pragma unroll
        for (int t = 0; t < 4; t++) {
            int idx = tid + t * 256;
            int r = idx >> 3, kc = (idx & 7) * 4;
            cp_async16g(smem_u32(As + stage * TSTAGE + r * TROW + kc),
                        A + (size_t)(bm + r) * lda + kbase + k0 + kc, 16);
        }
    };
    auto ldW = [&](int stage, int k0) {
        #pragma unroll
        for (int t = 0; t < 4; t++) {
            int idx = tid + t * 256;
            int r = idx >> 3, kc = (idx & 7) * 4;
            int n = bn + r;
            int ok = (n < N);
            cp_async16g(smem_u32(Ws + stage * TSTAGE + r * TROW + kc),
                        W + (size_t)(ok ? n : 0) * ldw + kbase + k0 + kc, ok ? 16 : 0);
        }
    };

    const int nk = Kchunk / TBK;
    ldA(0, 0); ldW(0, 0); cp_commit();

    for (int it = 0; it < nk; it++) {
        int stage = it & 1;
        if (it + 1 < nk) {
            ldA(stage ^ 1, (it + 1) * TBK);
            ldW(stage ^ 1, (it + 1) * TBK);
            cp_commit();
            cp_wait<1>();
        } else {
            cp_wait<0>();
        }
        __syncthreads();

        const uint32_t* Asu = (const uint32_t*)(As + stage * TSTAGE);
        const uint32_t* Wsu = (const uint32_t*)(Ws + stage * TSTAGE);

        #pragma unroll
        for (int kk = 0; kk < TBK; kk += 8) {
            uint32_t af[2][4];
            #pragma unroll
            for (int mt = 0; mt < 2; mt++) {
                int r = wm * 32 + mt * 16 + gid;
                const uint32_t* ap = Asu + r * TROW + kk + tig;
                af[mt][0] = ap[0];
                af[mt][1] = ap[8 * TROW];
                af[mt][2] = ap[4];
                af[mt][3] = ap[8 * TROW + 4];
            }
            uint32_t bfr[8][2];
            #pragma unroll
            for (int nt = 0; nt < 8; nt++) {
                int n = wn * 64 + nt * 8 + gid;
                const uint32_t* bp = Wsu + n * TROW + kk + tig;
                bfr[nt][0] = bp[0];
                bfr[nt][1] = bp[4];
            }
            #pragma unroll
            for (int mt = 0; mt < 2; mt++)
                #pragma unroll
                for (int nt = 0; nt < 8; nt++)
                    mma_tf32(acc[mt][nt], af[mt], bfr[nt]);
        }
        __syncthreads();
    }

    #pragma unroll
    for (int mt = 0; mt < 2; mt++) {
        int r0 = bm + wm * 32 + mt * 16 + gid;
        #pragma unroll
        for (int nt = 0; nt < 8; nt++) {
            int col = bn + wn * 64 + nt * 8 + tig * 2;
            #pragma unroll
            for (int h = 0; h < 2; h++) {
                int m = r0 + h * 8;
                #pragma unroll
                for (int q = 0; q < 2; q++) {
                    int n = col + q;
                    if (n < N) C[(size_t)m * ldc + n] = acc[mt][nt][h * 2 + q];
                }
            }
        }
    }
}

// sum the XPSPLIT partials -> xdbl
__global__ void __launch_bounds__(256)
xp_reduce(const float* __restrict__ p, float* __restrict__ o)
{
    const int i = blockIdx.x * 256 + threadIdx.x;
    const int S = Mrows * 96;
    float s = 0.f;
    #pragma unroll
    for (int z = 0; z < XPSPLIT; z++) s += p[(size_t)z * S + i];
    o[i] = s;
}

// =================== fp32 SIMT GEMM (dtproj, accuracy-critical) ============
#define BM 128
#define BN 128
#define BKs 16
#define TM 8
#define TN 8

__global__ void __launch_bounds__(256)
sgemm_softplus(const float* __restrict__ A, int lda,
               const float* __restrict__ W, int ldw,
               float* __restrict__ C, int ldc,
               int K, const float* __restrict__ bias)
{
    __shared__ float As[BKs][BM];
    __shared__ float Ws[BKs][BN];

    const int tid = threadIdx.x;
    const int bm = blockIdx.y * BM;
    const int bn = blockIdx.x * BN;
    const int tx = tid & 15;
    const int ty = tid >> 4;
    const int lr = tid >> 2;
    const int lc = (tid & 3) * 4;

    float acc[TM][TN];
    #pragma unroll
    for (int i = 0; i < TM; i++)
        #pragma unroll
        for (int j = 0; j < TN; j++) acc[i][j] = 0.f;

    for (int k0 = 0; k0 < K; k0 += BKs) {
        #pragma unroll
        for (int h = 0; h < 2; h++) {
            int r = lr + h * 64;
            float4 v = *(const float4*)(A + (size_t)(bm + r) * lda + k0 + lc);
            As[lc + 0][r] = v.x; As[lc + 1][r] = v.y;
            As[lc + 2][r] = v.z; As[lc + 3][r] = v.w;
        }
        #pragma unroll
        for (int h = 0; h < 2; h++) {
            int r = lr + h * 64;
            float4 v = *(const float4*)(W + (size_t)(bn + r) * ldw + k0 + lc);
            Ws[lc + 0][r] = v.x; Ws[lc + 1][r] = v.y;
            Ws[lc + 2][r] = v.z; Ws[lc + 3][r] = v.w;
        }
        __syncthreads();

        #pragma unroll
        for (int k = 0; k < BKs; k++) {
            float a[TM], b[TN];
            #pragma unroll
            for (int i = 0; i < TM; i++) a[i] = As[k][ty * TM + i];
            #pragma unroll
            for (int j = 0; j < TN; j++) b[j] = Ws[k][tx * TN + j];
            #pragma unroll
            for (int i = 0; i < TM; i++)
                #pragma unroll
                for (int j = 0; j < TN; j++)
                    acc[i][j] = fmaf(a[i], b[j], acc[i][j]);
        }
        __syncthreads();
    }

    #pragma unroll
    for (int i = 0; i < TM; i++) {
        int m = bm + ty * TM + i;
        #pragma unroll
        for (int j = 0; j < TN; j++) {
            int n = bn + tx * TN + j;
            float s = acc[i][j] + bias[n];
            C[(size_t)m * ldc + n] = fmaxf(s, 0.f) + log1pf(__expf(-fabsf(s)));
        }
    }
}

// ---------------- float -> half conversion ---------------------------------
__global__ void __launch_bounds__(256)
cvt_f2h(const float* __restrict__ s, __half* __restrict__ d, int n)
{
    int i = (blockIdx.x * 256 + threadIdx.x) * 4;
    if (i < n) {
        float4 v = *(const float4*)(s + i);
        __half2* p = (__half2*)(d + i);
        p[0] = __floats2half2_rn(v.x, v.y);
        p[1] = __floats2half2_rn(v.z, v.w);
    }
}

// ---------------- layernorm (fp16 out) -------------------------------------
__global__ void __launch_bounds__(256)
ln_kernel(const float* __restrict__ x, const float* __restrict__ w,
          const float* __restrict__ b, __half* __restrict__ y)
{
    const int row = blockIdx.x;
    const float* xr = x + (size_t)row * DM;
    __half* yr = y + (size_t)row * DM;
    const int tid = threadIdx.x;

    float vals[4];
    float s = 0.f, ss = 0.f;
    #pragma unroll
    for (int i = 0; i < 4; i++) {
        float v = xr[tid + i * 256];
        vals[i] = v;
        s += v; ss += v * v;
    }
    #pragma unroll
    for (int o = 16; o > 0; o >>= 1) {
        s  += __shfl_xor_sync(0xffffffffu, s, o);
        ss += __shfl_xor_sync(0xffffffffu, ss, o);
    }
    __shared__ float sh[16], shh[16];
    int wid = tid >> 5, ln = tid & 31;
    if (ln == 0) { sh[wid] = s; shh[wid] = ss; }
    __syncthreads();
    if (wid == 0) {
        float a = (ln < 8) ? sh[ln] : 0.f;
        float c = (ln < 8) ? shh[ln] : 0.f;
        #pragma unroll
        for (int o = 4; o > 0; o >>= 1) {
            a += __shfl_xor_sync(0xffffffffu, a, o);
            c += __shfl_xor_sync(0xffffffffu, c, o);
        }
        if (ln == 0) { sh[0] = a; shh[0] = c; }
    }
    __syncthreads();
    float mean = sh[0] * (1.f / DM);
    float var  = shh[0] * (1.f / DM) - mean * mean;
    float rstd = rsqrtf(var + 1e-5f);
    #pragma unroll
    for (int i = 0; i < 4; i++) {
        int c = tid + i * 256;
        yr[c] = __float2half((vals[i] - mean) * rstd * w[c] + b[c]);
    }
}

// -------- depthwise causal conv (K=4) + bias + silu ------------------------
__global__ void __launch_bounds__(256)
conv_silu_kernel(const float* __restrict__ xz, const float* __restrict__ cw,
                 const float* __restrict__ cb, float* __restrict__ xm)
{
    const int e  = blockIdx.x * 256 + threadIdx.x;
    const int t0 = blockIdx.y * 8;
    const int b  = blockIdx.z;
    const float4 w = *(const float4*)(cw + e * 4);
    const float bias = cb[e];
    const float* base = xz + (size_t)b * Lseq * (2 * Eexp) + e;

    float v[11];
    #pragma unroll
    for (int i = 0; i < 11; i++) {
        int t = t0 - 3 + i;
        v[i] = (t >= 0) ? base[(size_t)t * (2 * Eexp)] : 0.f;
    }
    #pragma unroll
    for (int j = 0; j < 8; j++) {
        float sacc = bias;
        sacc = fmaf(w.x, v[j],     sacc);
        sacc = fmaf(w.y, v[j + 1], sacc);
        sacc = fmaf(w.z, v[j + 2], sacc);
        sacc = fmaf(w.w, v[j + 3], sacc);
        float sv = sacc / (1.f + __expf(-sacc));
        xm[((size_t)b * Lseq + t0 + j) * Eexp + e] = sv;
    }
}

// ---------------- selective scan + gating (fp16 output) --------------------
__global__ void __launch_bounds__(256)
scan_kernel(const float* __restrict__ u,    const float* __restrict__ dt,
            const float* __restrict__ xdbl, const float* __restrict__ Alog,
            const float* __restrict__ Dp,   const float* __restrict__ xz,
            __half* __restrict__ yg)
{
    const int tid = threadIdx.x;
    const int grp = tid >> 4;
    const int n   = tid & 15;
    const int blk = blockIdx.x;
    const int b   = blk >> 7;
    const int e   = ((blk & 127) << 4) + grp;

    const float A = -__expf(Alog[e * Nst + n]);
    const float D = Dp[e];
    float h = 0.f;
    const size_t rbase = (size_t)b * Lseq;

    float dts = dt[rbase * Eexp + e];
    float us  = u [rbase * Eexp + e];
    float Bn  = xdbl[rbase * 96 + Rrank + n];
    float Cn  = xdbl[rbase * 96 + Rrank + Nst + n];

    for (int t = 0; t < Lseq; t++) {
        float dts_c = dts, us_c = us, Bn_c = Bn, Cn_c = Cn;
        if (t + 1 < Lseq) {
            size_t r = rbase + t + 1;
            dts = dt[r * Eexp + e];
            us  = u [r * Eexp + e];
            Bn  = xdbl[r * 96 + Rrank + n];
            Cn  = xdbl[r * 96 + Rrank + Nst + n];
        }
        float dA = __expf(dts_c * A);
        h = fmaf(dA, h, (dts_c * us_c) * Bn_c);
        float p = h * Cn_c;
        p += __shfl_xor_sync(0xffffffffu, p, 1);
        p += __shfl_xor_sync(0xffffffffu, p, 2);
        p += __shfl_xor_sync(0xffffffffu, p, 4);
        p += __shfl_xor_sync(0xffffffffu, p, 8);
        if (n == 0) {
            size_t r = rbase + t;
            float zv = xz[r * (2 * Eexp) + Eexp + e];
            float yv = fmaf(us_c, D, p);
            yg[r * Eexp + e] = __float2half(yv * (zv / (1.f + __expf(-zv))));
        }
    }
}

// ---------------- host driver ----------------------------------------------
extern "C" void kernel_launch(void* const* d_in, const int* in_sizes, int n_in,
                              void* d_out, int out_size)
{
    const float* x        = (const float*)d_in[0];
    const float* ip_w     = (const float*)d_in[2];
    const float* ip_b     = (const float*)d_in[3];
    const float* ln_w     = (const float*)d_in[4];
    const float* ln_b     = (const float*)d_in[5];
    const float* inproj_w = (const float*)d_in[6];
    const float* conv_w   = (const float*)d_in[7];
    const float* conv_b   = (const float*)d_in[8];
    const float* xproj_w  = (const float*)d_in[9];
    const float* dtproj_w = (const float*)d_in[10];
    const float* dtproj_b = (const float*)d_in[11];
    const float* A_log    = (const float*)d_in[12];
    const float* Dp       = (const float*)d_in[13];
    const float* outproj_w= (const float*)d_in[14];
    const float* fnorm_w  = (const float*)d_in[15];
    const float* fnorm_b  = (const float*)d_in[16];
    const float* op_w     = (const float*)d_in[17];
    const float* op_b     = (const float*)d_in[18];
    float* out = (float*)d_out;

    float *h, *xz, *xm, *xdbl, *xp, *part, *dtb;
    __half *hnh, *ygh, *xh, *wh;
    cudaGetSymbolAddress((void**)&h,    g_h);
    cudaGetSymbolAddress((void**)&xz,   g_xz);
    cudaGetSymbolAddress((void**)&xm,   g_xm);
    cudaGetSymbolAddress((void**)&xdbl, g_xdbl);
    cudaGetSymbolAddress((void**)&xp,   g_xp);
    cudaGetSymbolAddress((void**)&part, g_part);
    cudaGetSymbolAddress((void**)&dtb,  g_dt);
    cudaGetSymbolAddress((void**)&hnh,  g_hnh);
    cudaGetSymbolAddress((void**)&ygh,  g_ygh);
    cudaGetSymbolAddress((void**)&xh,   g_xh);
    cudaGetSymbolAddress((void**)&wh,   g_wh);

    cudaFuncSetAttribute(hgemm_nt<0>, cudaFuncAttributeMaxDynamicSharedMemorySize, HSMEM_TOTAL);
    cudaFuncSetAttribute(hgemm_nt<1>, cudaFuncAttributeMaxDynamicSharedMemorySize, HSMEM_TOTAL);
    cudaFuncSetAttribute(hgemm_nt<3>, cudaFuncAttributeMaxDynamicSharedMemorySize, HSMEM_TOTAL);
    cudaFuncSetAttribute(tgemm_nt_splitk, cudaFuncAttributeMaxDynamicSharedMemorySize, TGEMM_SMEM);

    auto cvt = [&](const float* s, __half* d, int n) {
        cvt_f2h<<<(n / 4 + 255) / 256, 256>>>(s, d, n);
    };
    cvt(x,         xh,               Mrows * DIN);
    cvt(ip_w,      wh + WOFF_IP,     DM * DIN);
    cvt(inproj_w,  wh + WOFF_INPROJ, NLAYER * 2 * Eexp * DM);
    cvt(outproj_w, wh + WOFF_OUTPROJ,NLAYER * DM * Eexp);
    cvt(op_w,      wh + WOFF_OP,     DIN * DM);

    // input projection: h = x @ ip_w^T + ip_b  (2048x1024 K=512), split-K x2
    hgemm_nt<0><<<dim3(DM / 128, Mrows / 128, 2), 256, HSMEM_TOTAL>>>(
        xh, DIN, wh + WOFF_IP, DIN, part, DM, Mrows, DIN / 2, nullptr);
    reduce_k<2, 0><<<(Mrows * DM / 4) / 256, 256>>>(part, ip_b, h, DM, Mrows * DM);

    for (int l = 0; l < NLAYER; l++) {
        ln_kernel<<<Mrows, 256>>>(h, ln_w + l * DM, ln_b + l * DM, hnh);

        // xz = hn @ inproj^T   (2048 x 4096 x 1024), 512 CTAs — no split
        hgemm_nt<0><<<dim3(2 * Eexp / 128, Mrows / 128), 256, HSMEM_TOTAL>>>(
            hnh, DM, wh + WOFF_INPROJ + (size_t)l * 2 * Eexp * DM, DM,
            xz, 2 * Eexp, Mrows, DM, nullptr);

        conv_silu_kernel<<<dim3(Eexp / 256, Lseq / 8, Bsz), 256>>>(
            xz, conv_w + l * Eexp * Kconv, conv_b + l * Eexp, xm);

        // x_dbl = xm @ xproj^T  (2048 x 96 x 2048), tf32 split-K x8
        tgemm_nt_splitk<<<dim3(1, Mrows / TBM, XPSPLIT), 256, TGEMM_SMEM>>>(
            xm, Eexp, xproj_w + (size_t)l * 96 * Eexp, Eexp,
            xp, 96, Mrows, 96, Eexp / XPSPLIT);
        xp_reduce<<<(Mrows * 96) / 256, 256>>>(xp, xdbl);

        // dt = softplus(x_dbl[:, :R] @ dtproj^T + dtproj_b) -- fp32
        sgemm_softplus<<<dim3(Eexp / BN, Mrows / BM), 256>>>(
            xdbl, 96, dtproj_w + (size_t)l * Eexp * Rrank, Rrank,
            dtb, Eexp, Rrank, dtproj_b + l * Eexp);

        scan_kernel<<<256, 256>>>(
            xm, dtb, xdbl, A_log + l * Eexp * Nst, Dp + l * Eexp, xz, ygh);

        // h += yg @ outproj^T  (2048x1024 K=2048), split-K x2
        hgemm_nt<0><<<dim3(DM / 128, Mrows / 128, 2), 256, HSMEM_TOTAL>>>(
            ygh, Eexp, wh + WOFF_OUTPROJ + (size_t)l * DM * Eexp, Eexp,
            part, DM, Mrows, Eexp / 2, nullptr);
        reduce_k<2, 1><<<(Mrows * DM / 4) / 256, 256>>>(part, nullptr, h, DM, Mrows * DM);
    }

    // final LN + output projection (2048x512 K=1024), split-K x4
    ln_kernel<<<Mrows, 256>>>(h, fnorm_w, fnorm_b, hnh);
    hgemm_nt<0><<<dim3(DIN / 128, Mrows / 128, 4), 256, HSMEM_TOTAL>>>(
        hnh, DM, wh + WOFF_OP, DM, part, DIN, Mrows, DM / 4, nullptr);
    reduce_k<4, 0><<<(Mrows * DIN / 4) / 256, 256>>>(part, op_b, out, DIN, Mrows * DIN);
}

// round 15
// speedup vs baseline: 2.8289x; 1.9864x over previous
#include <cuda_runtime.h>
#include <cuda_fp16.h>
#include <cuda_bf16.h>
#include <cstdint>

// Problem constants
#define Bsz 2
#define Lseq 1024
#define DIN 512
#define DM 1024
#define NLAYER 4
#define Eexp 2048
#define Nst 16
#define Rrank 64
#define Kconv 4
#define Mrows (Bsz*Lseq)   // 2048
#define XPSPLIT 8          // split-K factor for xproj

// ---------------- scratch (device globals; no allocation allowed) ----------
__device__ float g_h   [Mrows*DM];
__device__ float g_xz  [Mrows*2*Eexp];
__device__ float g_xm  [Mrows*Eexp];
__device__ float g_xdbl[Mrows*96];
__device__ float g_xp  [XPSPLIT*Mrows*128];  // xproj split-K partials (128-wide)
__device__ float g_part[4*Mrows*DIN];        // split-K partials (= 2*Mrows*DM)
__device__ float g_dt  [Mrows*Eexp];
__device__ __half g_hnh  [Mrows*DM];
__device__ __half g_ygh  [Mrows*Eexp];
__device__ __half g_xh   [Mrows*DIN];
__device__ __half g_xmh  [Mrows*Eexp];       // fp16 copy of xm (xproj A)
__device__ __half g_xdblh[Mrows*96];         // fp16 copy of xdbl (dtproj A)
__device__ __half g_xpwh [NLAYER*128*Eexp];  // padded fp16 xproj weights
__device__ __half g_dtwh [NLAYER*Eexp*Rrank];// fp16 dtproj weights
// converted weights: ip | inproj | outproj | op
#define WOFF_IP      0
#define WOFF_INPROJ  (WOFF_IP + DM*DIN)
#define WOFF_OUTPROJ (WOFF_INPROJ + NLAYER*2*Eexp*DM)
#define WOFF_OP      (WOFF_OUTPROJ + NLAYER*DM*Eexp)
#define WTOTAL       (WOFF_OP + DIN*DM)
__device__ __half g_wh[WTOTAL];

// ---------------- small PTX helpers ----------------------------------------
__device__ __forceinline__ uint32_t smem_u32(const void* p) {
    return (uint32_t)__cvta_generic_to_shared(p);
}
__device__ __forceinline__ void cp_async16(uint32_t dst, const void* src) {
    asm volatile("cp.async.cg.shared.global [%0], [%1], 16;\n"
                 :: "r"(dst), "l"(src));
}
__device__ __forceinline__ void cp_commit() {
    asm volatile("cp.async.commit_group;\n");
}
template<int NPend>
__device__ __forceinline__ void cp_wait() {
    asm volatile("cp.async.wait_group %0;\n" :: "n"(NPend));
}
__device__ __forceinline__ void ldsm_x4(uint32_t& r0, uint32_t& r1,
                                        uint32_t& r2, uint32_t& r3, uint32_t addr) {
    asm volatile("ldmatrix.sync.aligned.m8n8.x4.shared.b16 {%0,%1,%2,%3}, [%4];"
                 : "=r"(r0), "=r"(r1), "=r"(r2), "=r"(r3) : "r"(addr));
}
__device__ __forceinline__ void mma_f16(float* d, const uint32_t* a, const uint32_t* b) {
    asm volatile(
        "mma.sync.aligned.m16n8k16.row.col.f32.f16.f16.f32 "
        "{%0,%1,%2,%3}, {%4,%5,%6,%7}, {%8,%9}, {%0,%1,%2,%3};\n"
        : "+f"(d[0]), "+f"(d[1]), "+f"(d[2]), "+f"(d[3])
        : "r"(a[0]), "r"(a[1]), "r"(a[2]), "r"(a[3]), "r"(b[0]), "r"(b[1]));
}
__device__ __forceinline__ float softplus_f(float s) {
    return fmaxf(s, 0.f) + log1pf(__expf(-fabsf(s)));
}

// =================== fp16 tensor-core NT GEMM ==============================
// C[m,n] = sum_k A[m,k]*W[n,k]; 3-stage cp.async pipeline.
// Split-K via blockIdx.z: chunk kz covers K cols [kz*K,(kz+1)*K), out at
// C + kz*M*ldc.  EPI: 0 = store, 2 = softplus(acc + bias[n])
#define HRS 40                              // smem row stride in halfs (80 B)
#define HSTAGE_H (128*HRS)
#define HSTAGE_BYTES (HSTAGE_H*2)           // 10240
#define HSTAGES 3
#define HSMEM_TOTAL (2*HSTAGES*HSTAGE_BYTES)  // 61440

template<int EPI>
__global__ void __launch_bounds__(256, 2)
hgemm_nt(const __half* __restrict__ A, int lda,
         const __half* __restrict__ W, int ldw,
         float* __restrict__ C, int ldc,
         int M, int K, const float* __restrict__ bias)
{
    extern __shared__ char smem[];
    __half* As = (__half*)smem;
    __half* Ws = (__half*)(smem + HSTAGES * HSTAGE_BYTES);

    const int tid  = threadIdx.x;
    const int warp = tid >> 5, lane = tid & 31;
    const int bm   = blockIdx.y * 128;
    const int bn   = blockIdx.x * 128;
    const int koff = blockIdx.z * K;
    C += (size_t)blockIdx.z * M * ldc;
    const int wm   = warp & 3;
    const int wn   = warp >> 2;
    const int gid  = lane >> 2, tig = lane & 3;

    float acc[2][8][4];
    #pragma unroll
    for (int i = 0; i < 2; i++)
        #pragma unroll
        for (int j = 0; j < 8; j++)
            #pragma unroll
            for (int q = 0; q < 4; q++) acc[i][j][q] = 0.f;

    auto ldA = [&](int s, int kt) {
        #pragma unroll
        for (int t = 0; t < 2; t++) {
            int idx = tid + t * 256;
            int r = idx >> 2, g = idx & 3;
            cp_async16(smem_u32(As + s * HSTAGE_H + r * HRS + g * 8),
                       A + (size_t)(bm + r) * lda + koff + kt * 32 + g * 8);
        }
    };
    auto ldW = [&](int s, int kt) {
        #pragma unroll
        for (int t = 0; t < 2; t++) {
            int idx = tid + t * 256;
            int r = idx >> 2, g = idx & 3;
            cp_async16(smem_u32(Ws + s * HSTAGE_H + r * HRS + g * 8),
                       W + (size_t)(bn + r) * ldw + koff + kt * 32 + g * 8);
        }
    };

    const int nk = K / 32;
    ldA(0, 0); ldW(0, 0); cp_commit();
    ldA(1, 1); ldW(1, 1); cp_commit();

    const int arow = wm * 32 + (lane & 15);
    const int acol = (lane >> 4) << 3;
    const int brow = wn * 64 + (lane & 7) + ((lane & 16) >> 1);
    const int bcol = lane & 8;

    for (int it = 0; it < nk; it++) {
        const int s = it % HSTAGES;
        if (it == nk - 1) cp_wait<0>(); else cp_wait<1>();
        __syncthreads();

        const __half* Asb = As + s * HSTAGE_H;
        const __half* Wsb = Ws + s * HSTAGE_H;

        #pragma unroll
        for (int kk = 0; kk < 32; kk += 16) {
            uint32_t af[2][4];
            #pragma unroll
            for (int mt = 0; mt < 2; mt++)
                ldsm_x4(af[mt][0], af[mt][1], af[mt][2], af[mt][3],
                        smem_u32(Asb + (arow + mt * 16) * HRS + kk + acol));
            uint32_t bf[8][2];
            #pragma unroll
            for (int ntp = 0; ntp < 4; ntp++)
                ldsm_x4(bf[ntp * 2][0], bf[ntp * 2][1],
                        bf[ntp * 2 + 1][0], bf[ntp * 2 + 1][1],
                        smem_u32(Wsb + (brow + ntp * 16) * HRS + kk + bcol));
            #pragma unroll
            for (int mt = 0; mt < 2; mt++)
                #pragma unroll
                for (int nt = 0; nt < 8; nt++)
                    mma_f16(acc[mt][nt], af[mt], bf[nt]);
        }

        if (it + 2 < nk) {
            const int s2 = (it + 2) % HSTAGES;
            ldA(s2, it + 2); ldW(s2, it + 2); cp_commit();
        }
    }

    #pragma unroll
    for (int mt = 0; mt < 2; mt++) {
        int r0 = bm + wm * 32 + mt * 16 + gid;
        #pragma unroll
        for (int nt = 0; nt < 8; nt++) {
            int n0 = bn + wn * 64 + nt * 8 + tig * 2;
            #pragma unroll
            for (int hh = 0; hh < 2; hh++) {
                float* cp = C + (size_t)(r0 + hh * 8) * ldc + n0;
                float2 v = make_float2(acc[mt][nt][hh * 2], acc[mt][nt][hh * 2 + 1]);
                if (EPI == 2) {
                    v.x = softplus_f(v.x + bias[n0]);
                    v.y = softplus_f(v.y + bias[n0 + 1]);
                }
                *(float2*)cp = v;
            }
        }
    }
}

// -------- split-K reduce: C = sum_z part[z] (+bias | += ) -------------------
// MODE 0: C = sum + bias[n];  MODE 1: C += sum
template<int S, int MODE>
__global__ void __launch_bounds__(256)
reduce_k(const float* __restrict__ p, const float* __restrict__ bias,
         float* __restrict__ C, int N, int total)
{
    int i = (blockIdx.x * 256 + threadIdx.x) * 4;
    if (i >= total) return;
    float4 s = *(const float4*)(p + i);
    #pragma unroll
    for (int z = 1; z < S; z++) {
        float4 t = *(const float4*)(p + (size_t)z * total + i);
        s.x += t.x; s.y += t.y; s.z += t.z; s.w += t.w;
    }
    if (MODE == 0) {
        const float4 b = *(const float4*)(bias + (i % N));
        s.x += b.x; s.y += b.y; s.z += b.z; s.w += b.w;
        *(float4*)(C + i) = s;
    } else {
        float4 o = *(const float4*)(C + i);
        s.x += o.x; s.y += o.y; s.z += o.z; s.w += o.w;
        *(float4*)(C + i) = s;
    }
}

// sum xproj partials (128-wide) -> xdbl (96-wide, fp32 + fp16)
__global__ void __launch_bounds__(256)
xp_reduce(const float* __restrict__ p, float* __restrict__ o,
          __half* __restrict__ oh)
{
    const int i = blockIdx.x * 256 + threadIdx.x;   // 0 .. Mrows*96-1
    if (i >= Mrows * 96) return;
    const int row = i / 96, c = i - row * 96;
    const int S = Mrows * 128;
    float s = 0.f;
    #pragma unroll
    for (int z = 0; z < XPSPLIT; z++) s += p[(size_t)z * S + row * 128 + c];
    o[i] = s;
    oh[i] = __float2half(s);
}

// ---------------- float -> half conversion ---------------------------------
__global__ void __launch_bounds__(256)
cvt_f2h(const float* __restrict__ s, __half* __restrict__ d, int n)
{
    int i = (blockIdx.x * 256 + threadIdx.x) * 4;
    if (i < n) {
        float4 v = *(const float4*)(s + i);
        __half2* p = (__half2*)(d + i);
        p[0] = __floats2half2_rn(v.x, v.y);
        p[1] = __floats2half2_rn(v.z, v.w);
    }
}

// pad+convert xproj weights: [NL][96][E] f32 -> [NL][128][E] f16 (zero rows)
__global__ void __launch_bounds__(256)
cvt_pad_xpw(const float* __restrict__ s, __half* __restrict__ d)
{
    int i = (blockIdx.x * 256 + threadIdx.x) * 4;      // over NL*128*E
    if (i >= NLAYER * 128 * Eexp) return;
    int l = i / (128 * Eexp);
    int rem = i - l * 128 * Eexp;
    int r = rem / Eexp;
    int k = rem - r * Eexp;
    __half2* p = (__half2*)(d + i);
    if (r < 96) {
        float4 v = *(const float4*)(s + (size_t)l * 96 * Eexp + r * Eexp + k);
        p[0] = __floats2half2_rn(v.x, v.y);
        p[1] = __floats2half2_rn(v.z, v.w);
    } else {
        p[0] = __floats2half2_rn(0.f, 0.f);
        p[1] = __floats2half2_rn(0.f, 0.f);
    }
}

// ---------------- layernorm (fp16 out) -------------------------------------
__global__ void __launch_bounds__(256)
ln_kernel(const float* __restrict__ x, const float* __restrict__ w,
          const float* __restrict__ b, __half* __restrict__ y)
{
    const int row = blockIdx.x;
    const float* xr = x + (size_t)row * DM;
    __half* yr = y + (size_t)row * DM;
    const int tid = threadIdx.x;

    float vals[4];
    float s = 0.f, ss = 0.f;
    #pragma unroll
    for (int i = 0; i < 4; i++) {
        float v = xr[tid + i * 256];
        vals[i] = v;
        s += v; ss += v * v;
    }
    #pragma unroll
    for (int o = 16; o > 0; o >>= 1) {
        s  += __shfl_xor_sync(0xffffffffu, s, o);
        ss += __shfl_xor_sync(0xffffffffu, ss, o);
    }
    __shared__ float sh[16], shh[16];
    int wid = tid >> 5, ln = tid & 31;
    if (ln == 0) { sh[wid] = s; shh[wid] = ss; }
    __syncthreads();
    if (wid == 0) {
        float a = (ln < 8) ? sh[ln] : 0.f;
        float c = (ln < 8) ? shh[ln] : 0.f;
        #pragma unroll
        for (int o = 4; o > 0; o >>= 1) {
            a += __shfl_xor_sync(0xffffffffu, a, o);
            c += __shfl_xor_sync(0xffffffffu, c, o);
        }
        if (ln == 0) { sh[0] = a; shh[0] = c; }
    }
    __syncthreads();
    float mean = sh[0] * (1.f / DM);
    float var  = shh[0] * (1.f / DM) - mean * mean;
    float rstd = rsqrtf(var + 1e-5f);
    #pragma unroll
    for (int i = 0; i < 4; i++) {
        int c = tid + i * 256;
        yr[c] = __float2half((vals[i] - mean) * rstd * w[c] + b[c]);
    }
}

// -------- depthwise causal conv (K=4) + bias + silu, dual output -----------
__global__ void __launch_bounds__(256)
conv_silu_kernel(const float* __restrict__ xz, const float* __restrict__ cw,
                 const float* __restrict__ cb, float* __restrict__ xm,
                 __half* __restrict__ xmh)
{
    const int e  = blockIdx.x * 256 + threadIdx.x;
    const int t0 = blockIdx.y * 8;
    const int b  = blockIdx.z;
    const float4 w = *(const float4*)(cw + e * 4);
    const float bias = cb[e];
    const float* base = xz + (size_t)b * Lseq * (2 * Eexp) + e;

    float v[11];
    #pragma unroll
    for (int i = 0; i < 11; i++) {
        int t = t0 - 3 + i;
        v[i] = (t >= 0) ? base[(size_t)t * (2 * Eexp)] : 0.f;
    }
    #pragma unroll
    for (int j = 0; j < 8; j++) {
        float sacc = bias;
        sacc = fmaf(w.x, v[j],     sacc);
        sacc = fmaf(w.y, v[j + 1], sacc);
        sacc = fmaf(w.z, v[j + 2], sacc);
        sacc = fmaf(w.w, v[j + 3], sacc);
        float sv = sacc / (1.f + __expf(-sacc));
        size_t o = ((size_t)b * Lseq + t0 + j) * Eexp + e;
        xm[o]  = sv;
        xmh[o] = __float2half(sv);
    }
}

// ---------------- selective scan + gating (quad-prefetch) ------------------
__global__ void __launch_bounds__(256)
scan_kernel(const float* __restrict__ u,    const float* __restrict__ dt,
            const float* __restrict__ xdbl, const float* __restrict__ Alog,
            const float* __restrict__ Dp,   const float* __restrict__ xz,
            __half* __restrict__ yg)
{
    const int tid = threadIdx.x;
    const int grp = tid >> 4;
    const int n   = tid & 15;
    const int blk = blockIdx.x;
    const int b   = blk >> 7;
    const int e   = ((blk & 127) << 4) + grp;

    const float A = -__expf(Alog[e * Nst + n]);
    const float D = Dp[e];
    float h = 0.f;
    const size_t rbase = (size_t)b * Lseq;
    const bool lead = (n == 0);

    float cd[4], cu[4], cB[4], cC[4], cz[4];
    #pragma unroll
    for (int i = 0; i < 4; i++) {
        size_t r = rbase + i;
        cd[i] = dt[r * Eexp + e];
        cu[i] = u [r * Eexp + e];
        cB[i] = xdbl[r * 96 + Rrank + n];
        cC[i] = xdbl[r * 96 + Rrank + Nst + n];
        cz[i] = lead ? xz[r * (2 * Eexp) + Eexp + e] : 0.f;
    }

    for (int t0 = 0; t0 < Lseq; t0 += 4) {
        float nd[4], nu[4], nB[4], nC[4], nz[4];
        const bool more = (t0 + 4 < Lseq);
        if (more) {
            #pragma unroll
            for (int i = 0; i < 4; i++) {
                size_t r = rbase + t0 + 4 + i;
                nd[i] = dt[r * Eexp + e];
                nu[i] = u [r * Eexp + e];
                nB[i] = xdbl[r * 96 + Rrank + n];
                nC[i] = xdbl[r * 96 + Rrank + Nst + n];
                nz[i] = lead ? xz[r * (2 * Eexp) + Eexp + e] : 0.f;
            }
        }
        #pragma unroll
        for (int j = 0; j < 4; j++) {
            float dA = __expf(cd[j] * A);
            h = fmaf(dA, h, (cd[j] * cu[j]) * cB[j]);
            float p = h * cC[j];
            p += __shfl_xor_sync(0xffffffffu, p, 1);
            p += __shfl_xor_sync(0xffffffffu, p, 2);
            p += __shfl_xor_sync(0xffffffffu, p, 4);
            p += __shfl_xor_sync(0xffffffffu, p, 8);
            if (lead) {
                float zv = cz[j];
                float yv = fmaf(cu[j], D, p);
                yg[(rbase + t0 + j) * Eexp + e] =
                    __float2half(yv * (zv / (1.f + __expf(-zv))));
            }
        }
        if (more) {
            #pragma unroll
            for (int i = 0; i < 4; i++) {
                cd[i] = nd[i]; cu[i] = nu[i];
                cB[i] = nB[i]; cC[i] = nC[i]; cz[i] = nz[i];
            }
        }
    }
}

// ---------------- host driver ----------------------------------------------
extern "C" void kernel_launch(void* const* d_in, const int* in_sizes, int n_in,
                              void* d_out, int out_size)
{
    const float* x        = (const float*)d_in[0];
    const float* ip_w     = (const float*)d_in[2];
    const float* ip_b     = (const float*)d_in[3];
    const float* ln_w     = (const float*)d_in[4];
    const float* ln_b     = (const float*)d_in[5];
    const float* inproj_w = (const float*)d_in[6];
    const float* conv_w   = (const float*)d_in[7];
    const float* conv_b   = (const float*)d_in[8];
    const float* xproj_w  = (const float*)d_in[9];
    const float* dtproj_w = (const float*)d_in[10];
    const float* dtproj_b = (const float*)d_in[11];
    const float* A_log    = (const float*)d_in[12];
    const float* Dp       = (const float*)d_in[13];
    const float* outproj_w= (const float*)d_in[14];
    const float* fnorm_w  = (const float*)d_in[15];
    const float* fnorm_b  = (const float*)d_in[16];
    const float* op_w     = (const float*)d_in[17];
    const float* op_b     = (const float*)d_in[18];
    float* out = (float*)d_out;

    float *h, *xz, *xm, *xdbl, *xp, *part, *dtb;
    __half *hnh, *ygh, *xh, *wh, *xmh, *xdblh, *xpwh, *dtwh;
    cudaGetSymbolAddress((void**)&h,     g_h);
    cudaGetSymbolAddress((void**)&xz,    g_xz);
    cudaGetSymbolAddress((void**)&xm,    g_xm);
    cudaGetSymbolAddress((void**)&xdbl,  g_xdbl);
    cudaGetSymbolAddress((void**)&xp,    g_xp);
    cudaGetSymbolAddress((void**)&part,  g_part);
    cudaGetSymbolAddress((void**)&dtb,   g_dt);
    cudaGetSymbolAddress((void**)&hnh,   g_hnh);
    cudaGetSymbolAddress((void**)&ygh,   g_ygh);
    cudaGetSymbolAddress((void**)&xh,    g_xh);
    cudaGetSymbolAddress((void**)&wh,    g_wh);
    cudaGetSymbolAddress((void**)&xmh,   g_xmh);
    cudaGetSymbolAddress((void**)&xdblh, g_xdblh);
    cudaGetSymbolAddress((void**)&xpwh,  g_xpwh);
    cudaGetSymbolAddress((void**)&dtwh,  g_dtwh);

    cudaFuncSetAttribute(hgemm_nt<0>, cudaFuncAttributeMaxDynamicSharedMemorySize, HSMEM_TOTAL);
    cudaFuncSetAttribute(hgemm_nt<2>, cudaFuncAttributeMaxDynamicSharedMemorySize, HSMEM_TOTAL);

    auto cvt = [&](const float* s, __half* d, int n) {
        cvt_f2h<<<(n / 4 + 255) / 256, 256>>>(s, d, n);
    };
    cvt(x,         xh,               Mrows * DIN);
    cvt(ip_w,      wh + WOFF_IP,     DM * DIN);
    cvt(inproj_w,  wh + WOFF_INPROJ, NLAYER * 2 * Eexp * DM);
    cvt(outproj_w, wh + WOFF_OUTPROJ,NLAYER * DM * Eexp);
    cvt(op_w,      wh + WOFF_OP,     DIN * DM);
    cvt(dtproj_w,  dtwh,             NLAYER * Eexp * Rrank);
    cvt_pad_xpw<<<(NLAYER * 128 * Eexp / 4 + 255) / 256, 256>>>(xproj_w, xpwh);

    // input projection: h = x @ ip_w^T + ip_b  (2048x1024 K=512), split-K x2
    hgemm_nt<0><<<dim3(DM / 128, Mrows / 128, 2), 256, HSMEM_TOTAL>>>(
        xh, DIN, wh + WOFF_IP, DIN, part, DM, Mrows, DIN / 2, nullptr);
    reduce_k<2, 0><<<(Mrows * DM / 4) / 256, 256>>>(part, ip_b, h, DM, Mrows * DM);

    for (int l = 0; l < NLAYER; l++) {
        ln_kernel<<<Mrows, 256>>>(h, ln_w + l * DM, ln_b + l * DM, hnh);

        // xz = hn @ inproj^T   (2048 x 4096 x 1024)
        hgemm_nt<0><<<dim3(2 * Eexp / 128, Mrows / 128), 256, HSMEM_TOTAL>>>(
            hnh, DM, wh + WOFF_INPROJ + (size_t)l * 2 * Eexp * DM, DM,
            xz, 2 * Eexp, Mrows, DM, nullptr);

        conv_silu_kernel<<<dim3(Eexp / 256, Lseq / 8, Bsz), 256>>>(
            xz, conv_w + l * Eexp * Kconv, conv_b + l * Eexp, xm, xmh);

        // x_dbl = xm @ xproj^T (padded N=128), fp16 split-K x8
        hgemm_nt<0><<<dim3(1, Mrows / 128, XPSPLIT), 256, HSMEM_TOTAL>>>(
            xmh, Eexp, xpwh + (size_t)l * 128 * Eexp, Eexp,
            xp, 128, Mrows, Eexp / XPSPLIT, nullptr);
        xp_reduce<<<(Mrows * 96 + 255) / 256, 256>>>(xp, xdbl, xdblh);

        // dt = softplus(x_dbl[:, :R] @ dtproj^T + dtproj_b), fp16 tensor
        hgemm_nt<2><<<dim3(Eexp / 128, Mrows / 128), 256, HSMEM_TOTAL>>>(
            xdblh, 96, dtwh + (size_t)l * Eexp * Rrank, Rrank,
            dtb, Eexp, Mrows, Rrank, dtproj_b + l * Eexp);

        scan_kernel<<<256, 256>>>(
            xm, dtb, xdbl, A_log + l * Eexp * Nst, Dp + l * Eexp, xz, ygh);

        // h += yg @ outproj^T  (2048x1024 K=2048), split-K x2
        hgemm_nt<0><<<dim3(DM / 128, Mrows / 128, 2), 256, HSMEM_TOTAL>>>(
            ygh, Eexp, wh + WOFF_OUTPROJ + (size_t)l * DM * Eexp, Eexp,
            part, DM, Mrows, Eexp / 2, nullptr);
        reduce_k<2, 1><<<(Mrows * DM / 4) / 256, 256>>>(part, nullptr, h, DM, Mrows * DM);
    }

    // final LN + output projection (2048x512 K=1024), split-K x4
    ln_kernel<<<Mrows, 256>>>(h, fnorm_w, fnorm_b, hnh);
    hgemm_nt<0><<<dim3(DIN / 128, Mrows / 128, 4), 256, HSMEM_TOTAL>>>(
        hnh, DM, wh + WOFF_OP, DM, part, DIN, Mrows, DM / 4, nullptr);
    reduce_k<4, 0><<<(Mrows * DIN / 4) / 256, 256>>>(part, op_b, out, DIN, Mrows * DIN);
}